// round 1
// baseline (speedup 1.0000x reference)
#include <cuda_runtime.h>
#include <cuda_bf16.h>
#include <math.h>

// Problem dims
#define B_  2
#define S_  2048
#define H_  512
#define NH_ 8
#define DH_ 64
#define L_  6
#define FF_ 2048          // 4*H
#define M_  (B_*S_)       // 4096 tokens

// ---------------- device scratch (no cudaMalloc allowed) ----------------
__device__ float g_x  [M_*H_];
__device__ float g_q  [M_*H_];
__device__ float g_k  [M_*H_];
__device__ float g_v  [M_*H_];
__device__ float g_t  [M_*H_];
__device__ float g_t2 [M_*H_];
__device__ float g_res[M_*H_];
__device__ float g_h1 [M_*FF_];
__device__ float g_s  [(size_t)B_*NH_*S_*S_];   // 268 MB scores

// ---------------- embedding + sinusoidal posenc ----------------
__global__ __launch_bounds__(256) void embed_kernel(
    const int* __restrict__ src, const float* __restrict__ emb, float* __restrict__ x)
{
    int idx = blockIdx.x * 256 + threadIdx.x;        // over M_*H_
    int d   = idx & (H_ - 1);
    int tok = idx >> 9;
    int s   = tok & (S_ - 1);
    int j2  = (d >> 1) * 2;                          // arange(0,H,2) index value
    float div = powf(10000.0f, (float)j2 * (1.0f / (float)H_));
    float arg = (float)s / div;
    float pe  = (d & 1) ? cosf(arg) : sinf(arg);
    x[idx] = emb[(size_t)src[tok] * H_ + d] + pe;
}

// ---------------- generic SGEMM: C = A[M,K] @ B[K,N] + bias, optional ReLU ----
// BM=128, BN=128, BK=8, 256 threads, 8x8 per thread.
template<bool RELU>
__global__ __launch_bounds__(256) void gemm_bias_kernel(
    const float* __restrict__ A, const float* __restrict__ Bm,
    const float* __restrict__ bias, float* __restrict__ C,
    int M, int N, int K)
{
    __shared__ float As[8][128];
    __shared__ float Bs[8][128];
    int tid = threadIdx.x;
    int tx  = tid & 15, ty = tid >> 4;
    int brow = blockIdx.y * 128;
    int bcol = blockIdx.x * 128;
    const float* Ab = A  + (size_t)brow * K;
    const float* Bb = Bm + bcol;
    float acc[8][8];
    #pragma unroll
    for (int i = 0; i < 8; i++)
        #pragma unroll
        for (int j = 0; j < 8; j++) acc[i][j] = 0.f;

    // A-load mapping: thread -> one float4 of the 128x8 tile
    int ar_r = tid >> 1, ar_c = (tid & 1) * 4;
    // B-load mapping: thread -> one float4 of the 8x128 tile
    int br_r = tid >> 5, br_c = (tid & 31) * 4;

    for (int k0 = 0; k0 < K; k0 += 8) {
        float4 av = *(const float4*)&Ab[(size_t)ar_r * K + k0 + ar_c];
        As[ar_c + 0][ar_r] = av.x;
        As[ar_c + 1][ar_r] = av.y;
        As[ar_c + 2][ar_r] = av.z;
        As[ar_c + 3][ar_r] = av.w;
        float4 bv = *(const float4*)&Bb[(size_t)(k0 + br_r) * N + br_c];
        *(float4*)&Bs[br_r][br_c] = bv;
        __syncthreads();
        #pragma unroll
        for (int k = 0; k < 8; k++) {
            float ar[8], br[8];
            #pragma unroll
            for (int i = 0; i < 8; i++) ar[i] = As[k][ty * 8 + i];
            #pragma unroll
            for (int j = 0; j < 8; j++) br[j] = Bs[k][tx * 8 + j];
            #pragma unroll
            for (int i = 0; i < 8; i++)
                #pragma unroll
                for (int j = 0; j < 8; j++) acc[i][j] += ar[i] * br[j];
        }
        __syncthreads();
    }
    #pragma unroll
    for (int i = 0; i < 8; i++) {
        int r = brow + ty * 8 + i;
        #pragma unroll
        for (int j = 0; j < 8; j++) {
            int c = bcol + tx * 8 + j;
            float val = acc[i][j] + bias[c];
            if (RELU) val = fmaxf(val, 0.f);
            C[(size_t)r * N + c] = val;
        }
    }
}

// ---------------- attention scores: S = (Q @ K^T) * 0.125, mask ----------------
// per blockIdx.z = b*NH+h ; Q,K are [S_,DH_] slices with row stride H_
__global__ __launch_bounds__(256) void scores_kernel(
    const float* __restrict__ q, const float* __restrict__ k,
    const int* __restrict__ mask, float* __restrict__ sOut)
{
    __shared__ float As[8][128];
    __shared__ float Bs[8][128];
    int tid = threadIdx.x;
    int tx = tid & 15, ty = tid >> 4;
    int bh = blockIdx.z;
    int b = bh >> 3, h = bh & 7;
    int brow = blockIdx.y * 128;
    int bcol = blockIdx.x * 128;
    const float* Qb = q + (size_t)b * S_ * H_ + h * DH_ + (size_t)brow * H_;
    const float* Kb = k + (size_t)b * S_ * H_ + h * DH_ + (size_t)bcol * H_;
    float* Cb = sOut + (size_t)bh * S_ * S_;

    float acc[8][8];
    #pragma unroll
    for (int i = 0; i < 8; i++)
        #pragma unroll
        for (int j = 0; j < 8; j++) acc[i][j] = 0.f;

    int r_ = tid >> 1, c_ = (tid & 1) * 4;  // both tiles loaded 128 rows x 8 (k) cols

    for (int k0 = 0; k0 < DH_; k0 += 8) {
        float4 av = *(const float4*)&Qb[(size_t)r_ * H_ + k0 + c_];
        As[c_ + 0][r_] = av.x; As[c_ + 1][r_] = av.y;
        As[c_ + 2][r_] = av.z; As[c_ + 3][r_] = av.w;
        float4 bv = *(const float4*)&Kb[(size_t)r_ * H_ + k0 + c_];
        Bs[c_ + 0][r_] = bv.x; Bs[c_ + 1][r_] = bv.y;
        Bs[c_ + 2][r_] = bv.z; Bs[c_ + 3][r_] = bv.w;
        __syncthreads();
        #pragma unroll
        for (int kk = 0; kk < 8; kk++) {
            float ar[8], br[8];
            #pragma unroll
            for (int i = 0; i < 8; i++) ar[i] = As[kk][ty * 8 + i];
            #pragma unroll
            for (int j = 0; j < 8; j++) br[j] = Bs[kk][tx * 8 + j];
            #pragma unroll
            for (int i = 0; i < 8; i++)
                #pragma unroll
                for (int j = 0; j < 8; j++) acc[i][j] += ar[i] * br[j];
        }
        __syncthreads();
    }
    #pragma unroll
    for (int i = 0; i < 8; i++) {
        int r = brow + ty * 8 + i;
        #pragma unroll
        for (int j = 0; j < 8; j++) {
            int c = bcol + tx * 8 + j;
            float val = acc[i][j] * 0.125f;
            if (mask[b * S_ + c] == 0) val = -1e20f;
            Cb[(size_t)r * S_ + c] = val;
        }
    }
}

// ---------------- row softmax over 2048, in place ----------------
__global__ __launch_bounds__(256) void softmax_kernel(float* __restrict__ s)
{
    float* row = s + (size_t)blockIdx.x * S_;
    int tid = threadIdx.x;
    float v[8];
    float m = -1e30f;
    #pragma unroll
    for (int i = 0; i < 8; i++) { v[i] = row[tid + i * 256]; m = fmaxf(m, v[i]); }
    __shared__ float red[256];
    red[tid] = m; __syncthreads();
    for (int off = 128; off > 0; off >>= 1) {
        if (tid < off) red[tid] = fmaxf(red[tid], red[tid + off]);
        __syncthreads();
    }
    m = red[0];
    __syncthreads();
    float sum = 0.f;
    #pragma unroll
    for (int i = 0; i < 8; i++) { v[i] = expf(v[i] - m); sum += v[i]; }
    red[tid] = sum; __syncthreads();
    for (int off = 128; off > 0; off >>= 1) {
        if (tid < off) red[tid] += red[tid + off];
        __syncthreads();
    }
    float inv = 1.f / red[0];
    #pragma unroll
    for (int i = 0; i < 8; i++) row[tid + i * 256] = v[i] * inv;
}

// ---------------- AV: out[b, m, h*64+n] = attn[bh] @ V[bh]  ----------------
// BM=128, BN=64, BK=16, 256 thr, 8x4 per thread
__global__ __launch_bounds__(256) void av_kernel(
    const float* __restrict__ s, const float* __restrict__ v, float* __restrict__ out)
{
    __shared__ float As[16][128];
    __shared__ float Bs[16][64];
    int tid = threadIdx.x;
    int tx = tid & 15, ty = tid >> 4;
    int bh = blockIdx.z;
    int b = bh >> 3, h = bh & 7;
    int brow = blockIdx.y * 128;
    const float* Ab = s + (size_t)bh * S_ * S_ + (size_t)brow * S_;
    const float* Vb = v + (size_t)b * S_ * H_ + h * DH_;

    float acc[8][4];
    #pragma unroll
    for (int i = 0; i < 8; i++)
        #pragma unroll
        for (int j = 0; j < 4; j++) acc[i][j] = 0.f;

    // A tile: 128 x 16 => 512 float4s, 2 per thread
    // B tile: 16 x 64  => 256 float4s, 1 per thread
    int b_r = tid >> 4, b_c = (tid & 15) * 4;

    for (int k0 = 0; k0 < S_; k0 += 16) {
        #pragma unroll
        for (int i = 0; i < 2; i++) {
            int f4 = tid + i * 256;
            int r = f4 >> 2, c = (f4 & 3) * 4;
            float4 av = *(const float4*)&Ab[(size_t)r * S_ + k0 + c];
            As[c + 0][r] = av.x; As[c + 1][r] = av.y;
            As[c + 2][r] = av.z; As[c + 3][r] = av.w;
        }
        float4 bv = *(const float4*)&Vb[(size_t)(k0 + b_r) * H_ + b_c];
        *(float4*)&Bs[b_r][b_c] = bv;
        __syncthreads();
        #pragma unroll
        for (int kk = 0; kk < 16; kk++) {
            float ar[8], br[4];
            #pragma unroll
            for (int i = 0; i < 8; i++) ar[i] = As[kk][ty * 8 + i];
            #pragma unroll
            for (int j = 0; j < 4; j++) br[j] = Bs[kk][tx * 4 + j];
            #pragma unroll
            for (int i = 0; i < 8; i++)
                #pragma unroll
                for (int j = 0; j < 4; j++) acc[i][j] += ar[i] * br[j];
        }
        __syncthreads();
    }
    #pragma unroll
    for (int i = 0; i < 8; i++) {
        int m = brow + ty * 8 + i;
        int tok = b * S_ + m;
        #pragma unroll
        for (int j = 0; j < 4; j++) {
            int c = h * DH_ + tx * 4 + j;
            out[(size_t)tok * H_ + c] = acc[i][j];
        }
    }
}

// ---------------- residual + LayerNorm: out = xin + LN(y)*gamma + beta ----------------
__global__ __launch_bounds__(256) void add_ln_kernel(
    const float* __restrict__ xin, const float* __restrict__ y,
    const float* __restrict__ gamma, const float* __restrict__ beta,
    float* __restrict__ out)
{
    int t = blockIdx.x;
    int tid = threadIdx.x;
    const float* yr = y + (size_t)t * H_;
    float v0 = yr[tid], v1 = yr[tid + 256];
    __shared__ float s1[256], s2[256];
    s1[tid] = v0 + v1;
    s2[tid] = v0 * v0 + v1 * v1;
    __syncthreads();
    for (int off = 128; off > 0; off >>= 1) {
        if (tid < off) { s1[tid] += s1[tid + off]; s2[tid] += s2[tid + off]; }
        __syncthreads();
    }
    float mean = s1[0] * (1.f / (float)H_);
    float var  = s2[0] * (1.f / (float)H_) - mean * mean;
    float r = rsqrtf(var + 1e-5f);
    size_t base = (size_t)t * H_;
    out[base + tid]       = xin[base + tid]       + (v0 - mean) * r * gamma[tid]       + beta[tid];
    out[base + tid + 256] = xin[base + tid + 256] + (v1 - mean) * r * gamma[tid + 256] + beta[tid + 256];
}

__global__ __launch_bounds__(256) void copy_kernel(const float* __restrict__ in, float* __restrict__ out)
{
    int idx = blockIdx.x * 256 + threadIdx.x;
    out[idx] = in[idx];
}

// ---------------- host launcher ----------------
extern "C" void kernel_launch(void* const* d_in, const int* in_sizes, int n_in,
                              void* d_out, int out_size)
{
    const int*   src  = (const int*)  d_in[0];
    const int*   mask = (const int*)  d_in[1];
    const float* emb  = (const float*)d_in[2];
    const float* Wq   = (const float*)d_in[3];
    const float* bq   = (const float*)d_in[4];
    const float* Wk   = (const float*)d_in[5];
    const float* bk   = (const float*)d_in[6];
    const float* Wv   = (const float*)d_in[7];
    const float* bv   = (const float*)d_in[8];
    const float* Wo   = (const float*)d_in[9];
    const float* bo   = (const float*)d_in[10];
    const float* gamma= (const float*)d_in[11];
    const float* beta = (const float*)d_in[12];
    const float* W1   = (const float*)d_in[13];
    const float* b1   = (const float*)d_in[14];
    const float* W2   = (const float*)d_in[15];
    const float* b2   = (const float*)d_in[16];

    float *x, *q, *k, *v, *t, *t2, *res, *h1, *s;
    cudaGetSymbolAddress((void**)&x,   g_x);
    cudaGetSymbolAddress((void**)&q,   g_q);
    cudaGetSymbolAddress((void**)&k,   g_k);
    cudaGetSymbolAddress((void**)&v,   g_v);
    cudaGetSymbolAddress((void**)&t,   g_t);
    cudaGetSymbolAddress((void**)&t2,  g_t2);
    cudaGetSymbolAddress((void**)&res, g_res);
    cudaGetSymbolAddress((void**)&h1,  g_h1);
    cudaGetSymbolAddress((void**)&s,   g_s);

    embed_kernel<<<(M_ * H_) / 256, 256>>>(src, emb, x);

    dim3 gProj(H_ / 128, M_ / 128);        // (4, 32)
    dim3 gFfn1(FF_ / 128, M_ / 128);       // (16, 32)
    dim3 gScores(S_ / 128, S_ / 128, B_ * NH_);  // (16,16,16)
    dim3 gAv(1, S_ / 128, B_ * NH_);       // (1,16,16)

    for (int i = 0; i < L_; i++) {
        const float* Wq_i = Wq + (size_t)i * H_ * H_;
        const float* Wk_i = Wk + (size_t)i * H_ * H_;
        const float* Wv_i = Wv + (size_t)i * H_ * H_;
        const float* Wo_i = Wo + (size_t)i * H_ * H_;
        const float* W1_i = W1 + (size_t)i * H_ * FF_;
        const float* W2_i = W2 + (size_t)i * FF_ * H_;
        const float* bq_i = bq + i * H_;
        const float* bk_i = bk + i * H_;
        const float* bv_i = bv + i * H_;
        const float* bo_i = bo + i * H_;
        const float* b1_i = b1 + i * FF_;
        const float* b2_i = b2 + i * H_;
        const float* g_i  = gamma + i * H_;
        const float* be_i = beta  + i * H_;

        gemm_bias_kernel<false><<<gProj, 256>>>(x, Wq_i, bq_i, q, M_, H_, H_);
        gemm_bias_kernel<false><<<gProj, 256>>>(x, Wk_i, bk_i, k, M_, H_, H_);
        gemm_bias_kernel<false><<<gProj, 256>>>(x, Wv_i, bv_i, v, M_, H_, H_);

        scores_kernel<<<gScores, 256>>>(q, k, mask, s);
        softmax_kernel<<<B_ * NH_ * S_, 256>>>(s);
        av_kernel<<<gAv, 256>>>(s, v, t);

        gemm_bias_kernel<false><<<gProj, 256>>>(t, Wo_i, bo_i, t2, M_, H_, H_);
        add_ln_kernel<<<M_, 256>>>(x, t2, g_i, be_i, res);

        gemm_bias_kernel<true ><<<gFfn1, 256>>>(res, W1_i, b1_i, h1, M_, FF_, H_);
        gemm_bias_kernel<false><<<gProj, 256>>>(h1, W2_i, b2_i, t2, M_, H_, FF_);
        add_ln_kernel<<<M_, 256>>>(res, t2, g_i, be_i, x);
    }

    copy_kernel<<<(M_ * H_) / 256, 256>>>(x, (float*)d_out);
}

// round 2
// speedup vs baseline: 2.6921x; 2.6921x over previous
#include <cuda_runtime.h>
#include <cuda_bf16.h>
#include <math.h>

// Problem dims
#define B_  2
#define S_  2048
#define H_  512
#define NH_ 8
#define DH_ 64
#define L_  6
#define FF_ 2048          // 4*H
#define M_  (B_*S_)       // 4096 tokens

// ---------------- device scratch (no cudaMalloc allowed) ----------------
__device__ float g_x  [M_*H_];
__device__ float g_q  [M_*H_];
__device__ float g_k  [M_*H_];
__device__ float g_v  [M_*H_];
__device__ float g_t  [M_*H_];
__device__ float g_t2 [M_*H_];
__device__ float g_res[M_*H_];
__device__ float g_h1 [M_*FF_];
__device__ float g_s  [(size_t)B_*NH_*S_*S_];   // 268 MB scores

// ---------------- helpers ----------------
__device__ __forceinline__ float tf32r(float x) {
    float y;
    asm("cvt.rna.tf32.f32 %0, %1;" : "=f"(y) : "f"(x));
    return y;
}
__device__ __forceinline__ float4 tf32r4(float4 v) {
    v.x = tf32r(v.x); v.y = tf32r(v.y); v.z = tf32r(v.z); v.w = tf32r(v.w);
    return v;
}
__device__ __forceinline__ void mma_tf32(
    float& c0, float& c1, float& c2, float& c3,
    float a0, float a1, float a2, float a3, float b0, float b1)
{
    asm volatile(
        "mma.sync.aligned.m16n8k8.row.col.f32.tf32.tf32.f32 "
        "{%0,%1,%2,%3}, {%4,%5,%6,%7}, {%8,%9}, {%0,%1,%2,%3};\n"
        : "+f"(c0), "+f"(c1), "+f"(c2), "+f"(c3)
        : "r"(__float_as_uint(a0)), "r"(__float_as_uint(a1)),
          "r"(__float_as_uint(a2)), "r"(__float_as_uint(a3)),
          "r"(__float_as_uint(b0)), "r"(__float_as_uint(b1)));
}

// ---------------- embedding + sinusoidal posenc ----------------
__global__ __launch_bounds__(256) void embed_kernel(
    const int* __restrict__ src, const float* __restrict__ emb, float* __restrict__ x)
{
    int idx = blockIdx.x * 256 + threadIdx.x;        // over M_*H_
    int d   = idx & (H_ - 1);
    int tok = idx >> 9;
    int s   = tok & (S_ - 1);
    int j2  = (d >> 1) * 2;
    float div = powf(10000.0f, (float)j2 * (1.0f / (float)H_));
    float arg = (float)s / div;
    float pe  = (d & 1) ? cosf(arg) : sinf(arg);
    x[idx] = emb[(size_t)src[tok] * H_ + d] + pe;
}

// =========================================================================
// Tensor-core (tf32 HMMA) GEMM: C = A[M,K] @ W[K,N] + bias (+ReLU)
// BM=128 BN=128 BK=32, 256 threads = 8 warps (4x2), warp tile 32x64.
// As[128][36] (bank-free frag reads: (4m+k)%32 distinct)
// Bs[32][136]  (bank-free frag reads: (8k+n)%32 distinct)
// =========================================================================
#define AS_STRIDE 36
#define BS_STRIDE 136
template<bool RELU>
__global__ __launch_bounds__(256) void gemm_tc_kernel(
    const float* __restrict__ A, const float* __restrict__ W,
    const float* __restrict__ bias, float* __restrict__ C,
    int M, int N, int K)
{
    __shared__ float As[128 * AS_STRIDE];
    __shared__ float Bs[32 * BS_STRIDE];
    int tid  = threadIdx.x;
    int lane = tid & 31;
    int warp = tid >> 5;
    int warp_m = (warp >> 1) * 32;   // 0..96
    int warp_n = (warp & 1) * 64;    // 0 or 64
    int brow = blockIdx.y * 128;
    int bcol = blockIdx.x * 128;

    int lg = lane >> 2;   // groupID 0..7
    int lt = lane & 3;    // thread-in-group 0..3

    float acc[2][8][4];
    #pragma unroll
    for (int i = 0; i < 2; i++)
        #pragma unroll
        for (int j = 0; j < 8; j++)
            #pragma unroll
            for (int r = 0; r < 4; r++) acc[i][j][r] = 0.f;

    for (int k0 = 0; k0 < K; k0 += 32) {
        // load A tile 128x32 (row-major into As, tf32-rounded)
        #pragma unroll
        for (int i = 0; i < 4; i++) {
            int f4 = tid + i * 256;           // 0..1023
            int r = f4 >> 3, c = (f4 & 7) * 4;
            float4 v = *(const float4*)&A[(size_t)(brow + r) * K + k0 + c];
            *(float4*)&As[r * AS_STRIDE + c] = tf32r4(v);
        }
        // load B tile 32x128
        #pragma unroll
        for (int i = 0; i < 4; i++) {
            int f4 = tid + i * 256;
            int r = f4 >> 5, c = (f4 & 31) * 4;
            float4 v = *(const float4*)&W[(size_t)(k0 + r) * N + bcol + c];
            *(float4*)&Bs[r * BS_STRIDE + c] = tf32r4(v);
        }
        __syncthreads();

        #pragma unroll
        for (int kk = 0; kk < 32; kk += 8) {
            float af[2][4];
            #pragma unroll
            for (int i = 0; i < 2; i++) {
                int mb = warp_m + i * 16;
                af[i][0] = As[(mb + lg) * AS_STRIDE + kk + lt];
                af[i][1] = As[(mb + 8 + lg) * AS_STRIDE + kk + lt];
                af[i][2] = As[(mb + lg) * AS_STRIDE + kk + 4 + lt];
                af[i][3] = As[(mb + 8 + lg) * AS_STRIDE + kk + 4 + lt];
            }
            float bf[8][2];
            #pragma unroll
            for (int j = 0; j < 8; j++) {
                int nb = warp_n + j * 8 + lg;
                bf[j][0] = Bs[(kk + lt) * BS_STRIDE + nb];
                bf[j][1] = Bs[(kk + 4 + lt) * BS_STRIDE + nb];
            }
            #pragma unroll
            for (int i = 0; i < 2; i++)
                #pragma unroll
                for (int j = 0; j < 8; j++)
                    mma_tf32(acc[i][j][0], acc[i][j][1], acc[i][j][2], acc[i][j][3],
                             af[i][0], af[i][1], af[i][2], af[i][3],
                             bf[j][0], bf[j][1]);
        }
        __syncthreads();
    }

    // epilogue
    #pragma unroll
    for (int i = 0; i < 2; i++) {
        #pragma unroll
        for (int j = 0; j < 8; j++) {
            int col = bcol + warp_n + j * 8 + 2 * lt;
            float bx = bias[col], by = bias[col + 1];
            int r0 = brow + warp_m + i * 16 + lg;
            float2 v0 = make_float2(acc[i][j][0] + bx, acc[i][j][1] + by);
            float2 v1 = make_float2(acc[i][j][2] + bx, acc[i][j][3] + by);
            if (RELU) {
                v0.x = fmaxf(v0.x, 0.f); v0.y = fmaxf(v0.y, 0.f);
                v1.x = fmaxf(v1.x, 0.f); v1.y = fmaxf(v1.y, 0.f);
            }
            *(float2*)&C[(size_t)r0 * N + col]       = v0;
            *(float2*)&C[(size_t)(r0 + 8) * N + col] = v1;
        }
    }
}

// =========================================================================
// scores = (Q @ K^T) * 0.125 with mask.  Per blockIdx.z = b*NH+h.
// Both Q and K tiles stored [128][36]; K fragment read (4n+k)%32 bank-free.
// =========================================================================
__global__ __launch_bounds__(256) void scores_tc_kernel(
    const float* __restrict__ q, const float* __restrict__ k,
    const int* __restrict__ mask, float* __restrict__ sOut)
{
    __shared__ float Qs[128 * AS_STRIDE];
    __shared__ float Ks[128 * AS_STRIDE];
    int tid  = threadIdx.x;
    int lane = tid & 31;
    int warp = tid >> 5;
    int warp_m = (warp >> 1) * 32;
    int warp_n = (warp & 1) * 64;
    int bh = blockIdx.z;
    int b = bh >> 3, h = bh & 7;
    int brow = blockIdx.y * 128;
    int bcol = blockIdx.x * 128;
    const float* Qb = q + (size_t)b * S_ * H_ + h * DH_;
    const float* Kb = k + (size_t)b * S_ * H_ + h * DH_;
    float* Cb = sOut + (size_t)bh * S_ * S_;

    int lg = lane >> 2, lt = lane & 3;

    float acc[2][8][4];
    #pragma unroll
    for (int i = 0; i < 2; i++)
        #pragma unroll
        for (int j = 0; j < 8; j++)
            #pragma unroll
            for (int r = 0; r < 4; r++) acc[i][j][r] = 0.f;

    for (int k0 = 0; k0 < DH_; k0 += 32) {
        #pragma unroll
        for (int i = 0; i < 4; i++) {
            int f4 = tid + i * 256;
            int r = f4 >> 3, c = (f4 & 7) * 4;
            float4 v = *(const float4*)&Qb[(size_t)(brow + r) * H_ + k0 + c];
            *(float4*)&Qs[r * AS_STRIDE + c] = tf32r4(v);
            float4 w = *(const float4*)&Kb[(size_t)(bcol + r) * H_ + k0 + c];
            *(float4*)&Ks[r * AS_STRIDE + c] = tf32r4(w);
        }
        __syncthreads();

        #pragma unroll
        for (int kk = 0; kk < 32; kk += 8) {
            float af[2][4];
            #pragma unroll
            for (int i = 0; i < 2; i++) {
                int mb = warp_m + i * 16;
                af[i][0] = Qs[(mb + lg) * AS_STRIDE + kk + lt];
                af[i][1] = Qs[(mb + 8 + lg) * AS_STRIDE + kk + lt];
                af[i][2] = Qs[(mb + lg) * AS_STRIDE + kk + 4 + lt];
                af[i][3] = Qs[(mb + 8 + lg) * AS_STRIDE + kk + 4 + lt];
            }
            float bf[8][2];
            #pragma unroll
            for (int j = 0; j < 8; j++) {
                int nb = warp_n + j * 8 + lg;
                bf[j][0] = Ks[nb * AS_STRIDE + kk + lt];
                bf[j][1] = Ks[nb * AS_STRIDE + kk + 4 + lt];
            }
            #pragma unroll
            for (int i = 0; i < 2; i++)
                #pragma unroll
                for (int j = 0; j < 8; j++)
                    mma_tf32(acc[i][j][0], acc[i][j][1], acc[i][j][2], acc[i][j][3],
                             af[i][0], af[i][1], af[i][2], af[i][3],
                             bf[j][0], bf[j][1]);
        }
        __syncthreads();
    }

    #pragma unroll
    for (int i = 0; i < 2; i++) {
        #pragma unroll
        for (int j = 0; j < 8; j++) {
            int col = bcol + warp_n + j * 8 + 2 * lt;
            float mx = (mask[b * S_ + col]     == 0) ? -1e20f : 0.f;
            float my = (mask[b * S_ + col + 1] == 0) ? -1e20f : 0.f;
            int r0 = brow + warp_m + i * 16 + lg;
            float2 v0, v1;
            v0.x = (mx != 0.f) ? mx : acc[i][j][0] * 0.125f;
            v0.y = (my != 0.f) ? my : acc[i][j][1] * 0.125f;
            v1.x = (mx != 0.f) ? mx : acc[i][j][2] * 0.125f;
            v1.y = (my != 0.f) ? my : acc[i][j][3] * 0.125f;
            *(float2*)&Cb[(size_t)r0 * S_ + col]       = v0;
            *(float2*)&Cb[(size_t)(r0 + 8) * S_ + col] = v1;
        }
    }
}

// ---------------- row softmax over 2048, in place ----------------
__global__ __launch_bounds__(256) void softmax_kernel(float* __restrict__ s)
{
    float* row = s + (size_t)blockIdx.x * S_;
    int tid = threadIdx.x;
    float v[8];
    float m = -1e30f;
    #pragma unroll
    for (int i = 0; i < 8; i++) { v[i] = row[tid + i * 256]; m = fmaxf(m, v[i]); }
    __shared__ float red[256];
    red[tid] = m; __syncthreads();
    for (int off = 128; off > 0; off >>= 1) {
        if (tid < off) red[tid] = fmaxf(red[tid], red[tid + off]);
        __syncthreads();
    }
    m = red[0];
    __syncthreads();
    float sum = 0.f;
    #pragma unroll
    for (int i = 0; i < 8; i++) { v[i] = expf(v[i] - m); sum += v[i]; }
    red[tid] = sum; __syncthreads();
    for (int off = 128; off > 0; off >>= 1) {
        if (tid < off) red[tid] += red[tid + off];
        __syncthreads();
    }
    float inv = 1.f / red[0];
    #pragma unroll
    for (int i = 0; i < 8; i++) row[tid + i * 256] = v[i] * inv;
}

// =========================================================================
// AV: out[b, m, h*64+n] = attn[bh] @ V[bh]; BM=128 BN=64 BK=32, warp 32x32.
// Bs[32][72]: frag read (8k+n)%32 bank-free.
// =========================================================================
#define VS_STRIDE 72
__global__ __launch_bounds__(256) void av_tc_kernel(
    const float* __restrict__ s, const float* __restrict__ v, float* __restrict__ out)
{
    __shared__ float As[128 * AS_STRIDE];
    __shared__ float Bs[32 * VS_STRIDE];
    int tid  = threadIdx.x;
    int lane = tid & 31;
    int warp = tid >> 5;
    int warp_m = (warp >> 1) * 32;
    int warp_n = (warp & 1) * 32;
    int bh = blockIdx.z;
    int b = bh >> 3, h = bh & 7;
    int brow = blockIdx.y * 128;
    const float* Ab = s + (size_t)bh * S_ * S_ + (size_t)brow * S_;
    const float* Vb = v + (size_t)b * S_ * H_ + h * DH_;

    int lg = lane >> 2, lt = lane & 3;

    float acc[2][4][4];
    #pragma unroll
    for (int i = 0; i < 2; i++)
        #pragma unroll
        for (int j = 0; j < 4; j++)
            #pragma unroll
            for (int r = 0; r < 4; r++) acc[i][j][r] = 0.f;

    for (int k0 = 0; k0 < S_; k0 += 32) {
        #pragma unroll
        for (int i = 0; i < 4; i++) {
            int f4 = tid + i * 256;
            int r = f4 >> 3, c = (f4 & 7) * 4;
            float4 a = *(const float4*)&Ab[(size_t)r * S_ + k0 + c];
            *(float4*)&As[r * AS_STRIDE + c] = tf32r4(a);
        }
        #pragma unroll
        for (int i = 0; i < 2; i++) {
            int f4 = tid + i * 256;    // 0..511
            int r = f4 >> 4, c = (f4 & 15) * 4;
            float4 bvv = *(const float4*)&Vb[(size_t)(k0 + r) * H_ + c];
            *(float4*)&Bs[r * VS_STRIDE + c] = tf32r4(bvv);
        }
        __syncthreads();

        #pragma unroll
        for (int kk = 0; kk < 32; kk += 8) {
            float af[2][4];
            #pragma unroll
            for (int i = 0; i < 2; i++) {
                int mb = warp_m + i * 16;
                af[i][0] = As[(mb + lg) * AS_STRIDE + kk + lt];
                af[i][1] = As[(mb + 8 + lg) * AS_STRIDE + kk + lt];
                af[i][2] = As[(mb + lg) * AS_STRIDE + kk + 4 + lt];
                af[i][3] = As[(mb + 8 + lg) * AS_STRIDE + kk + 4 + lt];
            }
            float bf[4][2];
            #pragma unroll
            for (int j = 0; j < 4; j++) {
                int nb = warp_n + j * 8 + lg;
                bf[j][0] = Bs[(kk + lt) * VS_STRIDE + nb];
                bf[j][1] = Bs[(kk + 4 + lt) * VS_STRIDE + nb];
            }
            #pragma unroll
            for (int i = 0; i < 2; i++)
                #pragma unroll
                for (int j = 0; j < 4; j++)
                    mma_tf32(acc[i][j][0], acc[i][j][1], acc[i][j][2], acc[i][j][3],
                             af[i][0], af[i][1], af[i][2], af[i][3],
                             bf[j][0], bf[j][1]);
        }
        __syncthreads();
    }

    #pragma unroll
    for (int i = 0; i < 2; i++) {
        #pragma unroll
        for (int j = 0; j < 4; j++) {
            int col = h * DH_ + warp_n + j * 8 + 2 * lt;
            int m0 = brow + warp_m + i * 16 + lg;
            int tok0 = b * S_ + m0;
            *(float2*)&out[(size_t)tok0 * H_ + col] =
                make_float2(acc[i][j][0], acc[i][j][1]);
            *(float2*)&out[(size_t)(tok0 + 8) * H_ + col] =
                make_float2(acc[i][j][2], acc[i][j][3]);
        }
    }
}

// ---------------- residual + LayerNorm: out = xin + LN(y)*gamma + beta ----------------
__global__ __launch_bounds__(256) void add_ln_kernel(
    const float* __restrict__ xin, const float* __restrict__ y,
    const float* __restrict__ gamma, const float* __restrict__ beta,
    float* __restrict__ out)
{
    int t = blockIdx.x;
    int tid = threadIdx.x;
    const float* yr = y + (size_t)t * H_;
    float v0 = yr[tid], v1 = yr[tid + 256];
    __shared__ float s1[256], s2[256];
    s1[tid] = v0 + v1;
    s2[tid] = v0 * v0 + v1 * v1;
    __syncthreads();
    for (int off = 128; off > 0; off >>= 1) {
        if (tid < off) { s1[tid] += s1[tid + off]; s2[tid] += s2[tid + off]; }
        __syncthreads();
    }
    float mean = s1[0] * (1.f / (float)H_);
    float var  = s2[0] * (1.f / (float)H_) - mean * mean;
    float r = rsqrtf(var + 1e-5f);
    size_t base = (size_t)t * H_;
    out[base + tid]       = xin[base + tid]       + (v0 - mean) * r * gamma[tid]       + beta[tid];
    out[base + tid + 256] = xin[base + tid + 256] + (v1 - mean) * r * gamma[tid + 256] + beta[tid + 256];
}

__global__ __launch_bounds__(256) void copy_kernel(const float* __restrict__ in, float* __restrict__ out)
{
    int idx = blockIdx.x * 256 + threadIdx.x;
    out[idx] = in[idx];
}

// ---------------- host launcher ----------------
extern "C" void kernel_launch(void* const* d_in, const int* in_sizes, int n_in,
                              void* d_out, int out_size)
{
    const int*   src  = (const int*)  d_in[0];
    const int*   mask = (const int*)  d_in[1];
    const float* emb  = (const float*)d_in[2];
    const float* Wq   = (const float*)d_in[3];
    const float* bq   = (const float*)d_in[4];
    const float* Wk   = (const float*)d_in[5];
    const float* bk   = (const float*)d_in[6];
    const float* Wv   = (const float*)d_in[7];
    const float* bv   = (const float*)d_in[8];
    const float* Wo   = (const float*)d_in[9];
    const float* bo   = (const float*)d_in[10];
    const float* gamma= (const float*)d_in[11];
    const float* beta = (const float*)d_in[12];
    const float* W1   = (const float*)d_in[13];
    const float* b1   = (const float*)d_in[14];
    const float* W2   = (const float*)d_in[15];
    const float* b2   = (const float*)d_in[16];

    float *x, *q, *k, *v, *t, *t2, *res, *h1, *s;
    cudaGetSymbolAddress((void**)&x,   g_x);
    cudaGetSymbolAddress((void**)&q,   g_q);
    cudaGetSymbolAddress((void**)&k,   g_k);
    cudaGetSymbolAddress((void**)&v,   g_v);
    cudaGetSymbolAddress((void**)&t,   g_t);
    cudaGetSymbolAddress((void**)&t2,  g_t2);
    cudaGetSymbolAddress((void**)&res, g_res);
    cudaGetSymbolAddress((void**)&h1,  g_h1);
    cudaGetSymbolAddress((void**)&s,   g_s);

    embed_kernel<<<(M_ * H_) / 256, 256>>>(src, emb, x);

    dim3 gProj(H_ / 128, M_ / 128);              // (4, 32)
    dim3 gFfn1(FF_ / 128, M_ / 128);             // (16, 32)
    dim3 gScores(S_ / 128, S_ / 128, B_ * NH_);  // (16,16,16)
    dim3 gAv(1, S_ / 128, B_ * NH_);             // (1,16,16)

    for (int i = 0; i < L_; i++) {
        const float* Wq_i = Wq + (size_t)i * H_ * H_;
        const float* Wk_i = Wk + (size_t)i * H_ * H_;
        const float* Wv_i = Wv + (size_t)i * H_ * H_;
        const float* Wo_i = Wo + (size_t)i * H_ * H_;
        const float* W1_i = W1 + (size_t)i * H_ * FF_;
        const float* W2_i = W2 + (size_t)i * FF_ * H_;
        const float* bq_i = bq + i * H_;
        const float* bk_i = bk + i * H_;
        const float* bv_i = bv + i * H_;
        const float* bo_i = bo + i * H_;
        const float* b1_i = b1 + i * FF_;
        const float* b2_i = b2 + i * H_;
        const float* g_i  = gamma + i * H_;
        const float* be_i = beta  + i * H_;

        gemm_tc_kernel<false><<<gProj, 256>>>(x, Wq_i, bq_i, q, M_, H_, H_);
        gemm_tc_kernel<false><<<gProj, 256>>>(x, Wk_i, bk_i, k, M_, H_, H_);
        gemm_tc_kernel<false><<<gProj, 256>>>(x, Wv_i, bv_i, v, M_, H_, H_);

        scores_tc_kernel<<<gScores, 256>>>(q, k, mask, s);
        softmax_kernel<<<B_ * NH_ * S_, 256>>>(s);
        av_tc_kernel<<<gAv, 256>>>(s, v, t);

        gemm_tc_kernel<false><<<gProj, 256>>>(t, Wo_i, bo_i, t2, M_, H_, H_);
        add_ln_kernel<<<M_, 256>>>(x, t2, g_i, be_i, res);

        gemm_tc_kernel<true ><<<gFfn1, 256>>>(res, W1_i, b1_i, h1, M_, FF_, H_);
        gemm_tc_kernel<false><<<gProj, 256>>>(h1, W2_i, b2_i, t2, M_, H_, FF_);
        add_ln_kernel<<<M_, 256>>>(res, t2, g_i, be_i, x);
    }

    copy_kernel<<<(M_ * H_) / 256, 256>>>(x, (float*)d_out);
}

// round 3
// speedup vs baseline: 3.2054x; 1.1907x over previous
#include <cuda_runtime.h>
#include <cuda_bf16.h>
#include <math.h>

// Problem dims
#define B_  2
#define S_  2048
#define H_  512
#define NH_ 8
#define DH_ 64
#define L_  6
#define FF_ 2048          // 4*H
#define M_  (B_*S_)       // 4096 tokens

// ---------------- device scratch (no cudaMalloc allowed) ----------------
__device__ float g_x  [M_*H_];
__device__ float g_q  [M_*H_];
__device__ float g_k  [M_*H_];
__device__ float g_v  [M_*H_];
__device__ float g_t  [M_*H_];
__device__ float g_t2 [M_*H_];
__device__ float g_res[M_*H_];
__device__ float g_h1 [M_*FF_];
__device__ float g_s  [(size_t)B_*NH_*S_*S_];   // 268 MB scores

// ---------------- helpers ----------------
__device__ __forceinline__ float tf32r(float x) {
    float y;
    asm("cvt.rna.tf32.f32 %0, %1;" : "=f"(y) : "f"(x));
    return y;
}
__device__ __forceinline__ float4 tf32r4(float4 v) {
    v.x = tf32r(v.x); v.y = tf32r(v.y); v.z = tf32r(v.z); v.w = tf32r(v.w);
    return v;
}
__device__ __forceinline__ void mma_tf32(
    float& c0, float& c1, float& c2, float& c3,
    float a0, float a1, float a2, float a3, float b0, float b1)
{
    asm volatile(
        "mma.sync.aligned.m16n8k8.row.col.f32.tf32.tf32.f32 "
        "{%0,%1,%2,%3}, {%4,%5,%6,%7}, {%8,%9}, {%0,%1,%2,%3};\n"
        : "+f"(c0), "+f"(c1), "+f"(c2), "+f"(c3)
        : "r"(__float_as_uint(a0)), "r"(__float_as_uint(a1)),
          "r"(__float_as_uint(a2)), "r"(__float_as_uint(a3)),
          "r"(__float_as_uint(b0)), "r"(__float_as_uint(b1)));
}

// ---------------- embedding + sinusoidal posenc ----------------
__global__ __launch_bounds__(256) void embed_kernel(
    const int* __restrict__ src, const float* __restrict__ emb, float* __restrict__ x)
{
    int idx = blockIdx.x * 256 + threadIdx.x;
    int d   = idx & (H_ - 1);
    int tok = idx >> 9;
    int s   = tok & (S_ - 1);
    int j2  = (d >> 1) * 2;
    float div = powf(10000.0f, (float)j2 * (1.0f / (float)H_));
    float arg = (float)s / div;
    float pe  = (d & 1) ? cosf(arg) : sinf(arg);
    x[idx] = emb[(size_t)src[tok] * H_ + d] + pe;
}

#define AS_STRIDE 36
#define BS_STRIDE 72

// =========================================================================
// Pipelined tf32 GEMM: C = A[M,K] @ W[K,N] + bias (+ReLU)
// BM=128 BN=64 BK=32, 256 thr = 8 warps (4x2), warp tile 32x32.
// 2-stage smem double buffer, next tile loaded to regs during compute.
// QKV fusion: if W2/W3 non-null, blockIdx.z selects weight/bias/output.
// =========================================================================
template<bool RELU>
__global__ __launch_bounds__(256, 2) void gemm_tc_kernel(
    const float* __restrict__ A,
    const float* __restrict__ Wa, const float* __restrict__ Wb, const float* __restrict__ Wc,
    const float* __restrict__ ba, const float* __restrict__ bb, const float* __restrict__ bc,
    float* __restrict__ Ca, float* __restrict__ Cb_, float* __restrict__ Cc,
    int M, int N, int K)
{
    __shared__ float As[2][128 * AS_STRIDE];
    __shared__ float Bs[2][32 * BS_STRIDE];
    int tid  = threadIdx.x;
    int lane = tid & 31;
    int warp = tid >> 5;
    int warp_m = (warp >> 1) * 32;   // 0,32,64,96
    int warp_n = (warp & 1) * 32;    // 0,32
    int brow = blockIdx.y * 128;
    int bcol = blockIdx.x * 64;
    int z = blockIdx.z;
    const float* W    = (z == 0) ? Wa : (z == 1) ? Wb : Wc;
    const float* bias = (z == 0) ? ba : (z == 1) ? bb : bc;
    float*       C    = (z == 0) ? Ca : (z == 1) ? Cb_ : Cc;

    int lg = lane >> 2, lt = lane & 3;

    // load index mapping
    int a_r = tid >> 3, a_c = (tid & 7) * 4;      // A: 128x32, 4 f4/thread (stride 32 rows)
    int b_r = tid >> 4, b_c = (tid & 15) * 4;     // B: 32x64,  2 f4/thread (stride 16 rows)

    float4 abuf[4], bbuf[2];

    // prologue: load k0=0
    #pragma unroll
    for (int i = 0; i < 4; i++)
        abuf[i] = *(const float4*)&A[(size_t)(brow + a_r + i * 32) * K + a_c];
    #pragma unroll
    for (int i = 0; i < 2; i++)
        bbuf[i] = *(const float4*)&W[(size_t)(b_r + i * 16) * N + bcol + b_c];
    #pragma unroll
    for (int i = 0; i < 4; i++)
        *(float4*)&As[0][(a_r + i * 32) * AS_STRIDE + a_c] = tf32r4(abuf[i]);
    #pragma unroll
    for (int i = 0; i < 2; i++)
        *(float4*)&Bs[0][(b_r + i * 16) * BS_STRIDE + b_c] = tf32r4(bbuf[i]);
    __syncthreads();

    float acc[2][4][4];
    #pragma unroll
    for (int i = 0; i < 2; i++)
        #pragma unroll
        for (int j = 0; j < 4; j++)
            #pragma unroll
            for (int r = 0; r < 4; r++) acc[i][j][r] = 0.f;

    int buf = 0;
    for (int k0 = 32; k0 < K; k0 += 32) {
        // issue next-tile loads
        #pragma unroll
        for (int i = 0; i < 4; i++)
            abuf[i] = *(const float4*)&A[(size_t)(brow + a_r + i * 32) * K + k0 + a_c];
        #pragma unroll
        for (int i = 0; i < 2; i++)
            bbuf[i] = *(const float4*)&W[(size_t)(k0 + b_r + i * 16) * N + bcol + b_c];

        // compute on current buffer
        #pragma unroll
        for (int kk = 0; kk < 32; kk += 8) {
            float af[2][4];
            #pragma unroll
            for (int i = 0; i < 2; i++) {
                int mb = warp_m + i * 16;
                af[i][0] = As[buf][(mb + lg) * AS_STRIDE + kk + lt];
                af[i][1] = As[buf][(mb + 8 + lg) * AS_STRIDE + kk + lt];
                af[i][2] = As[buf][(mb + lg) * AS_STRIDE + kk + 4 + lt];
                af[i][3] = As[buf][(mb + 8 + lg) * AS_STRIDE + kk + 4 + lt];
            }
            float bf[4][2];
            #pragma unroll
            for (int j = 0; j < 4; j++) {
                int nb = warp_n + j * 8 + lg;
                bf[j][0] = Bs[buf][(kk + lt) * BS_STRIDE + nb];
                bf[j][1] = Bs[buf][(kk + 4 + lt) * BS_STRIDE + nb];
            }
            #pragma unroll
            for (int i = 0; i < 2; i++)
                #pragma unroll
                for (int j = 0; j < 4; j++)
                    mma_tf32(acc[i][j][0], acc[i][j][1], acc[i][j][2], acc[i][j][3],
                             af[i][0], af[i][1], af[i][2], af[i][3],
                             bf[j][0], bf[j][1]);
        }

        // store next tile into other buffer
        #pragma unroll
        for (int i = 0; i < 4; i++)
            *(float4*)&As[buf ^ 1][(a_r + i * 32) * AS_STRIDE + a_c] = tf32r4(abuf[i]);
        #pragma unroll
        for (int i = 0; i < 2; i++)
            *(float4*)&Bs[buf ^ 1][(b_r + i * 16) * BS_STRIDE + b_c] = tf32r4(bbuf[i]);
        __syncthreads();
        buf ^= 1;
    }

    // final tile compute
    #pragma unroll
    for (int kk = 0; kk < 32; kk += 8) {
        float af[2][4];
        #pragma unroll
        for (int i = 0; i < 2; i++) {
            int mb = warp_m + i * 16;
            af[i][0] = As[buf][(mb + lg) * AS_STRIDE + kk + lt];
            af[i][1] = As[buf][(mb + 8 + lg) * AS_STRIDE + kk + lt];
            af[i][2] = As[buf][(mb + lg) * AS_STRIDE + kk + 4 + lt];
            af[i][3] = As[buf][(mb + 8 + lg) * AS_STRIDE + kk + 4 + lt];
        }
        float bf[4][2];
        #pragma unroll
        for (int j = 0; j < 4; j++) {
            int nb = warp_n + j * 8 + lg;
            bf[j][0] = Bs[buf][(kk + lt) * BS_STRIDE + nb];
            bf[j][1] = Bs[buf][(kk + 4 + lt) * BS_STRIDE + nb];
        }
        #pragma unroll
        for (int i = 0; i < 2; i++)
            #pragma unroll
            for (int j = 0; j < 4; j++)
                mma_tf32(acc[i][j][0], acc[i][j][1], acc[i][j][2], acc[i][j][3],
                         af[i][0], af[i][1], af[i][2], af[i][3],
                         bf[j][0], bf[j][1]);
    }

    // epilogue
    #pragma unroll
    for (int i = 0; i < 2; i++) {
        #pragma unroll
        for (int j = 0; j < 4; j++) {
            int col = bcol + warp_n + j * 8 + 2 * lt;
            float bx = bias[col], by = bias[col + 1];
            int r0 = brow + warp_m + i * 16 + lg;
            float2 v0 = make_float2(acc[i][j][0] + bx, acc[i][j][1] + by);
            float2 v1 = make_float2(acc[i][j][2] + bx, acc[i][j][3] + by);
            if (RELU) {
                v0.x = fmaxf(v0.x, 0.f); v0.y = fmaxf(v0.y, 0.f);
                v1.x = fmaxf(v1.x, 0.f); v1.y = fmaxf(v1.y, 0.f);
            }
            *(float2*)&C[(size_t)r0 * N + col]       = v0;
            *(float2*)&C[(size_t)(r0 + 8) * N + col] = v1;
        }
    }
}

// =========================================================================
// scores = (Q @ K^T) * 0.125 with mask.  (K=64: only 2 k-iters, store-bound)
// =========================================================================
__global__ __launch_bounds__(256) void scores_tc_kernel(
    const float* __restrict__ q, const float* __restrict__ k,
    const int* __restrict__ mask, float* __restrict__ sOut)
{
    __shared__ float Qs[128 * AS_STRIDE];
    __shared__ float Ks[128 * AS_STRIDE];
    int tid  = threadIdx.x;
    int lane = tid & 31;
    int warp = tid >> 5;
    int warp_m = (warp >> 1) * 32;
    int warp_n = (warp & 1) * 64;
    int bh = blockIdx.z;
    int b = bh >> 3, h = bh & 7;
    int brow = blockIdx.y * 128;
    int bcol = blockIdx.x * 128;
    const float* Qb = q + (size_t)b * S_ * H_ + h * DH_;
    const float* Kb = k + (size_t)b * S_ * H_ + h * DH_;
    float* Cb = sOut + (size_t)bh * S_ * S_;

    int lg = lane >> 2, lt = lane & 3;

    float acc[2][8][4];
    #pragma unroll
    for (int i = 0; i < 2; i++)
        #pragma unroll
        for (int j = 0; j < 8; j++)
            #pragma unroll
            for (int r = 0; r < 4; r++) acc[i][j][r] = 0.f;

    for (int k0 = 0; k0 < DH_; k0 += 32) {
        #pragma unroll
        for (int i = 0; i < 4; i++) {
            int f4 = tid + i * 256;
            int r = f4 >> 3, c = (f4 & 7) * 4;
            float4 v = *(const float4*)&Qb[(size_t)(brow + r) * H_ + k0 + c];
            *(float4*)&Qs[r * AS_STRIDE + c] = tf32r4(v);
            float4 w = *(const float4*)&Kb[(size_t)(bcol + r) * H_ + k0 + c];
            *(float4*)&Ks[r * AS_STRIDE + c] = tf32r4(w);
        }
        __syncthreads();

        #pragma unroll
        for (int kk = 0; kk < 32; kk += 8) {
            float af[2][4];
            #pragma unroll
            for (int i = 0; i < 2; i++) {
                int mb = warp_m + i * 16;
                af[i][0] = Qs[(mb + lg) * AS_STRIDE + kk + lt];
                af[i][1] = Qs[(mb + 8 + lg) * AS_STRIDE + kk + lt];
                af[i][2] = Qs[(mb + lg) * AS_STRIDE + kk + 4 + lt];
                af[i][3] = Qs[(mb + 8 + lg) * AS_STRIDE + kk + 4 + lt];
            }
            float bf[8][2];
            #pragma unroll
            for (int j = 0; j < 8; j++) {
                int nb = warp_n + j * 8 + lg;
                bf[j][0] = Ks[nb * AS_STRIDE + kk + lt];
                bf[j][1] = Ks[nb * AS_STRIDE + kk + 4 + lt];
            }
            #pragma unroll
            for (int i = 0; i < 2; i++)
                #pragma unroll
                for (int j = 0; j < 8; j++)
                    mma_tf32(acc[i][j][0], acc[i][j][1], acc[i][j][2], acc[i][j][3],
                             af[i][0], af[i][1], af[i][2], af[i][3],
                             bf[j][0], bf[j][1]);
        }
        __syncthreads();
    }

    #pragma unroll
    for (int i = 0; i < 2; i++) {
        #pragma unroll
        for (int j = 0; j < 8; j++) {
            int col = bcol + warp_n + j * 8 + 2 * lt;
            float mx = (mask[b * S_ + col]     == 0) ? -1e20f : 0.f;
            float my = (mask[b * S_ + col + 1] == 0) ? -1e20f : 0.f;
            int r0 = brow + warp_m + i * 16 + lg;
            float2 v0, v1;
            v0.x = (mx != 0.f) ? mx : acc[i][j][0] * 0.125f;
            v0.y = (my != 0.f) ? my : acc[i][j][1] * 0.125f;
            v1.x = (mx != 0.f) ? mx : acc[i][j][2] * 0.125f;
            v1.y = (my != 0.f) ? my : acc[i][j][3] * 0.125f;
            *(float2*)&Cb[(size_t)r0 * S_ + col]       = v0;
            *(float2*)&Cb[(size_t)(r0 + 8) * S_ + col] = v1;
        }
    }
}

// ---------------- row softmax over 2048, in place ----------------
__global__ __launch_bounds__(256) void softmax_kernel(float* __restrict__ s)
{
    float* row = s + (size_t)blockIdx.x * S_;
    int tid = threadIdx.x;
    float v[8];
    float m = -1e30f;
    #pragma unroll
    for (int i = 0; i < 8; i++) { v[i] = row[tid + i * 256]; m = fmaxf(m, v[i]); }
    __shared__ float red[256];
    red[tid] = m; __syncthreads();
    for (int off = 128; off > 0; off >>= 1) {
        if (tid < off) red[tid] = fmaxf(red[tid], red[tid + off]);
        __syncthreads();
    }
    m = red[0];
    __syncthreads();
    float sum = 0.f;
    #pragma unroll
    for (int i = 0; i < 8; i++) { v[i] = expf(v[i] - m); sum += v[i]; }
    red[tid] = sum; __syncthreads();
    for (int off = 128; off > 0; off >>= 1) {
        if (tid < off) red[tid] += red[tid + off];
        __syncthreads();
    }
    float inv = 1.f / red[0];
    #pragma unroll
    for (int i = 0; i < 8; i++) row[tid + i * 256] = v[i] * inv;
}

// =========================================================================
// AV: out[b, m, h*64+n] = attn[bh] @ V[bh]; BM=128 BN=64 BK=32, pipelined.
// =========================================================================
__global__ __launch_bounds__(256, 2) void av_tc_kernel(
    const float* __restrict__ s, const float* __restrict__ v, float* __restrict__ out)
{
    __shared__ float As[2][128 * AS_STRIDE];
    __shared__ float Bs[2][32 * BS_STRIDE];
    int tid  = threadIdx.x;
    int lane = tid & 31;
    int warp = tid >> 5;
    int warp_m = (warp >> 1) * 32;
    int warp_n = (warp & 1) * 32;
    int bh = blockIdx.z;
    int b = bh >> 3, h = bh & 7;
    int brow = blockIdx.y * 128;
    const float* Ab = s + (size_t)bh * S_ * S_ + (size_t)brow * S_;
    const float* Vb = v + (size_t)b * S_ * H_ + h * DH_;

    int lg = lane >> 2, lt = lane & 3;
    int a_r = tid >> 3, a_c = (tid & 7) * 4;
    int b_r = tid >> 4, b_c = (tid & 15) * 4;

    float4 abuf[4], bbuf[2];
    #pragma unroll
    for (int i = 0; i < 4; i++)
        abuf[i] = *(const float4*)&Ab[(size_t)(a_r + i * 32) * S_ + a_c];
    #pragma unroll
    for (int i = 0; i < 2; i++)
        bbuf[i] = *(const float4*)&Vb[(size_t)(b_r + i * 16) * H_ + b_c];
    #pragma unroll
    for (int i = 0; i < 4; i++)
        *(float4*)&As[0][(a_r + i * 32) * AS_STRIDE + a_c] = tf32r4(abuf[i]);
    #pragma unroll
    for (int i = 0; i < 2; i++)
        *(float4*)&Bs[0][(b_r + i * 16) * BS_STRIDE + b_c] = tf32r4(bbuf[i]);
    __syncthreads();

    float acc[2][4][4];
    #pragma unroll
    for (int i = 0; i < 2; i++)
        #pragma unroll
        for (int j = 0; j < 4; j++)
            #pragma unroll
            for (int r = 0; r < 4; r++) acc[i][j][r] = 0.f;

    int buf = 0;
    for (int k0 = 32; k0 < S_; k0 += 32) {
        #pragma unroll
        for (int i = 0; i < 4; i++)
            abuf[i] = *(const float4*)&Ab[(size_t)(a_r + i * 32) * S_ + k0 + a_c];
        #pragma unroll
        for (int i = 0; i < 2; i++)
            bbuf[i] = *(const float4*)&Vb[(size_t)(k0 + b_r + i * 16) * H_ + b_c];

        #pragma unroll
        for (int kk = 0; kk < 32; kk += 8) {
            float af[2][4];
            #pragma unroll
            for (int i = 0; i < 2; i++) {
                int mb = warp_m + i * 16;
                af[i][0] = As[buf][(mb + lg) * AS_STRIDE + kk + lt];
                af[i][1] = As[buf][(mb + 8 + lg) * AS_STRIDE + kk + lt];
                af[i][2] = As[buf][(mb + lg) * AS_STRIDE + kk + 4 + lt];
                af[i][3] = As[buf][(mb + 8 + lg) * AS_STRIDE + kk + 4 + lt];
            }
            float bf[4][2];
            #pragma unroll
            for (int j = 0; j < 4; j++) {
                int nb = warp_n + j * 8 + lg;
                bf[j][0] = Bs[buf][(kk + lt) * BS_STRIDE + nb];
                bf[j][1] = Bs[buf][(kk + 4 + lt) * BS_STRIDE + nb];
            }
            #pragma unroll
            for (int i = 0; i < 2; i++)
                #pragma unroll
                for (int j = 0; j < 4; j++)
                    mma_tf32(acc[i][j][0], acc[i][j][1], acc[i][j][2], acc[i][j][3],
                             af[i][0], af[i][1], af[i][2], af[i][3],
                             bf[j][0], bf[j][1]);
        }

        #pragma unroll
        for (int i = 0; i < 4; i++)
            *(float4*)&As[buf ^ 1][(a_r + i * 32) * AS_STRIDE + a_c] = tf32r4(abuf[i]);
        #pragma unroll
        for (int i = 0; i < 2; i++)
            *(float4*)&Bs[buf ^ 1][(b_r + i * 16) * BS_STRIDE + b_c] = tf32r4(bbuf[i]);
        __syncthreads();
        buf ^= 1;
    }

    #pragma unroll
    for (int kk = 0; kk < 32; kk += 8) {
        float af[2][4];
        #pragma unroll
        for (int i = 0; i < 2; i++) {
            int mb = warp_m + i * 16;
            af[i][0] = As[buf][(mb + lg) * AS_STRIDE + kk + lt];
            af[i][1] = As[buf][(mb + 8 + lg) * AS_STRIDE + kk + lt];
            af[i][2] = As[buf][(mb + lg) * AS_STRIDE + kk + 4 + lt];
            af[i][3] = As[buf][(mb + 8 + lg) * AS_STRIDE + kk + 4 + lt];
        }
        float bf[4][2];
        #pragma unroll
        for (int j = 0; j < 4; j++) {
            int nb = warp_n + j * 8 + lg;
            bf[j][0] = Bs[buf][(kk + lt) * BS_STRIDE + nb];
            bf[j][1] = Bs[buf][(kk + 4 + lt) * BS_STRIDE + nb];
        }
        #pragma unroll
        for (int i = 0; i < 2; i++)
            #pragma unroll
            for (int j = 0; j < 4; j++)
                mma_tf32(acc[i][j][0], acc[i][j][1], acc[i][j][2], acc[i][j][3],
                         af[i][0], af[i][1], af[i][2], af[i][3],
                         bf[j][0], bf[j][1]);
    }

    #pragma unroll
    for (int i = 0; i < 2; i++) {
        #pragma unroll
        for (int j = 0; j < 4; j++) {
            int col = h * DH_ + warp_n + j * 8 + 2 * lt;
            int m0 = brow + warp_m + i * 16 + lg;
            int tok0 = b * S_ + m0;
            *(float2*)&out[(size_t)tok0 * H_ + col] =
                make_float2(acc[i][j][0], acc[i][j][1]);
            *(float2*)&out[(size_t)(tok0 + 8) * H_ + col] =
                make_float2(acc[i][j][2], acc[i][j][3]);
        }
    }
}

// ---------------- residual + LayerNorm ----------------
__global__ __launch_bounds__(256) void add_ln_kernel(
    const float* __restrict__ xin, const float* __restrict__ y,
    const float* __restrict__ gamma, const float* __restrict__ beta,
    float* __restrict__ out)
{
    int t = blockIdx.x;
    int tid = threadIdx.x;
    const float* yr = y + (size_t)t * H_;
    float v0 = yr[tid], v1 = yr[tid + 256];
    __shared__ float s1[256], s2[256];
    s1[tid] = v0 + v1;
    s2[tid] = v0 * v0 + v1 * v1;
    __syncthreads();
    for (int off = 128; off > 0; off >>= 1) {
        if (tid < off) { s1[tid] += s1[tid + off]; s2[tid] += s2[tid + off]; }
        __syncthreads();
    }
    float mean = s1[0] * (1.f / (float)H_);
    float var  = s2[0] * (1.f / (float)H_) - mean * mean;
    float r = rsqrtf(var + 1e-5f);
    size_t base = (size_t)t * H_;
    out[base + tid]       = xin[base + tid]       + (v0 - mean) * r * gamma[tid]       + beta[tid];
    out[base + tid + 256] = xin[base + tid + 256] + (v1 - mean) * r * gamma[tid + 256] + beta[tid + 256];
}

__global__ __launch_bounds__(256) void copy_kernel(const float* __restrict__ in, float* __restrict__ out)
{
    int idx = blockIdx.x * 256 + threadIdx.x;
    out[idx] = in[idx];
}

// ---------------- host launcher ----------------
extern "C" void kernel_launch(void* const* d_in, const int* in_sizes, int n_in,
                              void* d_out, int out_size)
{
    const int*   src  = (const int*)  d_in[0];
    const int*   mask = (const int*)  d_in[1];
    const float* emb  = (const float*)d_in[2];
    const float* Wq   = (const float*)d_in[3];
    const float* bq   = (const float*)d_in[4];
    const float* Wk   = (const float*)d_in[5];
    const float* bk   = (const float*)d_in[6];
    const float* Wv   = (const float*)d_in[7];
    const float* bv   = (const float*)d_in[8];
    const float* Wo   = (const float*)d_in[9];
    const float* bo   = (const float*)d_in[10];
    const float* gamma= (const float*)d_in[11];
    const float* beta = (const float*)d_in[12];
    const float* W1   = (const float*)d_in[13];
    const float* b1   = (const float*)d_in[14];
    const float* W2   = (const float*)d_in[15];
    const float* b2   = (const float*)d_in[16];

    float *x, *q, *k, *v, *t, *t2, *res, *h1, *s;
    cudaGetSymbolAddress((void**)&x,   g_x);
    cudaGetSymbolAddress((void**)&q,   g_q);
    cudaGetSymbolAddress((void**)&k,   g_k);
    cudaGetSymbolAddress((void**)&v,   g_v);
    cudaGetSymbolAddress((void**)&t,   g_t);
    cudaGetSymbolAddress((void**)&t2,  g_t2);
    cudaGetSymbolAddress((void**)&res, g_res);
    cudaGetSymbolAddress((void**)&h1,  g_h1);
    cudaGetSymbolAddress((void**)&s,   g_s);

    embed_kernel<<<(M_ * H_) / 256, 256>>>(src, emb, x);

    dim3 gQKV (H_ / 64,  M_ / 128, 3);           // (8, 32, 3)
    dim3 gProj(H_ / 64,  M_ / 128, 1);           // (8, 32)
    dim3 gFfn1(FF_ / 64, M_ / 128, 1);           // (32, 32)
    dim3 gScores(S_ / 128, S_ / 128, B_ * NH_);  // (16,16,16)
    dim3 gAv(1, S_ / 128, B_ * NH_);             // (1,16,16)

    for (int i = 0; i < L_; i++) {
        const float* Wq_i = Wq + (size_t)i * H_ * H_;
        const float* Wk_i = Wk + (size_t)i * H_ * H_;
        const float* Wv_i = Wv + (size_t)i * H_ * H_;
        const float* Wo_i = Wo + (size_t)i * H_ * H_;
        const float* W1_i = W1 + (size_t)i * H_ * FF_;
        const float* W2_i = W2 + (size_t)i * FF_ * H_;
        const float* bq_i = bq + i * H_;
        const float* bk_i = bk + i * H_;
        const float* bv_i = bv + i * H_;
        const float* bo_i = bo + i * H_;
        const float* b1_i = b1 + i * FF_;
        const float* b2_i = b2 + i * H_;
        const float* g_i  = gamma + i * H_;
        const float* be_i = beta  + i * H_;

        // fused QKV projections
        gemm_tc_kernel<false><<<gQKV, 256>>>(x, Wq_i, Wk_i, Wv_i, bq_i, bk_i, bv_i,
                                             q, k, v, M_, H_, H_);

        scores_tc_kernel<<<gScores, 256>>>(q, k, mask, s);
        softmax_kernel<<<B_ * NH_ * S_, 256>>>(s);
        av_tc_kernel<<<gAv, 256>>>(s, v, t);

        gemm_tc_kernel<false><<<gProj, 256>>>(t, Wo_i, Wo_i, Wo_i, bo_i, bo_i, bo_i,
                                              t2, t2, t2, M_, H_, H_);
        add_ln_kernel<<<M_, 256>>>(x, t2, g_i, be_i, res);

        gemm_tc_kernel<true ><<<gFfn1, 256>>>(res, W1_i, W1_i, W1_i, b1_i, b1_i, b1_i,
                                              h1, h1, h1, M_, FF_, H_);
        gemm_tc_kernel<false><<<gProj, 256>>>(h1, W2_i, W2_i, W2_i, b2_i, b2_i, b2_i,
                                              t2, t2, t2, M_, H_, FF_);
        add_ln_kernel<<<M_, 256>>>(res, t2, g_i, be_i, x);
    }

    copy_kernel<<<(M_ * H_) / 256, 256>>>(x, (float*)d_out);
}

// round 4
// speedup vs baseline: 4.4817x; 1.3981x over previous
#include <cuda_runtime.h>
#include <cuda_bf16.h>
#include <math.h>

// Problem dims
#define B_  2
#define S_  2048
#define H_  512
#define NH_ 8
#define DH_ 64
#define L_  6
#define FF_ 2048          // 4*H
#define M_  (B_*S_)       // 4096 tokens

// ---------------- device scratch (no cudaMalloc allowed) ----------------
__device__ float g_x  [M_*H_];
__device__ float g_q  [M_*H_];
__device__ float g_k  [M_*H_];
__device__ float g_v  [M_*H_];
__device__ float g_t  [M_*H_];
__device__ float g_t2 [M_*H_];
__device__ float g_res[M_*H_];
__device__ float g_h1 [M_*FF_];
__device__ float g_mb [M_];          // mask bias: 0 or -1e20 per (b,s)

// ---------------- helpers ----------------
__device__ __forceinline__ float tf32r(float x) {
    float y;
    asm("cvt.rna.tf32.f32 %0, %1;" : "=f"(y) : "f"(x));
    return y;
}
__device__ __forceinline__ float4 tf32r4(float4 v) {
    v.x = tf32r(v.x); v.y = tf32r(v.y); v.z = tf32r(v.z); v.w = tf32r(v.w);
    return v;
}
__device__ __forceinline__ void mma_tf32(
    float& c0, float& c1, float& c2, float& c3,
    float a0, float a1, float a2, float a3, float b0, float b1)
{
    asm volatile(
        "mma.sync.aligned.m16n8k8.row.col.f32.tf32.tf32.f32 "
        "{%0,%1,%2,%3}, {%4,%5,%6,%7}, {%8,%9}, {%0,%1,%2,%3};\n"
        : "+f"(c0), "+f"(c1), "+f"(c2), "+f"(c3)
        : "r"(__float_as_uint(a0)), "r"(__float_as_uint(a1)),
          "r"(__float_as_uint(a2)), "r"(__float_as_uint(a3)),
          "r"(__float_as_uint(b0)), "r"(__float_as_uint(b1)));
}
__device__ __forceinline__ void cp_async16(float* dst, const float* src) {
    unsigned s = (unsigned)__cvta_generic_to_shared(dst);
    asm volatile("cp.async.cg.shared.global [%0], [%1], 16;" :: "r"(s), "l"(src));
}
__device__ __forceinline__ void cp_commit() {
    asm volatile("cp.async.commit_group;");
}

// ---------------- embedding + sinusoidal posenc ----------------
__global__ __launch_bounds__(256) void embed_kernel(
    const int* __restrict__ src, const float* __restrict__ emb, float* __restrict__ x)
{
    int idx = blockIdx.x * 256 + threadIdx.x;
    int d   = idx & (H_ - 1);
    int tok = idx >> 9;
    int s   = tok & (S_ - 1);
    int j2  = (d >> 1) * 2;
    float div = powf(10000.0f, (float)j2 * (1.0f / (float)H_));
    float arg = (float)s / div;
    float pe  = (d & 1) ? cosf(arg) : sinf(arg);
    x[idx] = emb[(size_t)src[tok] * H_ + d] + pe;
}

__global__ __launch_bounds__(256) void maskbias_kernel(
    const int* __restrict__ mask, float* __restrict__ mb)
{
    int i = blockIdx.x * 256 + threadIdx.x;
    if (i < M_) mb[i] = mask[i] ? 0.f : -1e20f;
}

#define AS_STRIDE 36
#define BS_STRIDE 72

// =========================================================================
// Pipelined tf32 GEMM: C = A[M,K] @ W[K,N] + bias (+ReLU) (+tf32-round out)
// BM=128 BN=64 BK=32, 256 thr = 8 warps (4x2), warp tile 32x32.
// =========================================================================
template<bool RELU, bool ROUND>
__global__ __launch_bounds__(256, 2) void gemm_tc_kernel(
    const float* __restrict__ A,
    const float* __restrict__ Wa, const float* __restrict__ Wb, const float* __restrict__ Wc,
    const float* __restrict__ ba, const float* __restrict__ bb, const float* __restrict__ bc,
    float* __restrict__ Ca, float* __restrict__ Cb_, float* __restrict__ Cc,
    int M, int N, int K)
{
    __shared__ float As[2][128 * AS_STRIDE];
    __shared__ float Bs[2][32 * BS_STRIDE];
    int tid  = threadIdx.x;
    int lane = tid & 31;
    int warp = tid >> 5;
    int warp_m = (warp >> 1) * 32;
    int warp_n = (warp & 1) * 32;
    int brow = blockIdx.y * 128;
    int bcol = blockIdx.x * 64;
    int z = blockIdx.z;
    const float* W    = (z == 0) ? Wa : (z == 1) ? Wb : Wc;
    const float* bias = (z == 0) ? ba : (z == 1) ? bb : bc;
    float*       C    = (z == 0) ? Ca : (z == 1) ? Cb_ : Cc;

    int lg = lane >> 2, lt = lane & 3;
    int a_r = tid >> 3, a_c = (tid & 7) * 4;
    int b_r = tid >> 4, b_c = (tid & 15) * 4;

    float4 abuf[4], bbuf[2];

    #pragma unroll
    for (int i = 0; i < 4; i++)
        abuf[i] = *(const float4*)&A[(size_t)(brow + a_r + i * 32) * K + a_c];
    #pragma unroll
    for (int i = 0; i < 2; i++)
        bbuf[i] = *(const float4*)&W[(size_t)(b_r + i * 16) * N + bcol + b_c];
    #pragma unroll
    for (int i = 0; i < 4; i++)
        *(float4*)&As[0][(a_r + i * 32) * AS_STRIDE + a_c] = tf32r4(abuf[i]);
    #pragma unroll
    for (int i = 0; i < 2; i++)
        *(float4*)&Bs[0][(b_r + i * 16) * BS_STRIDE + b_c] = tf32r4(bbuf[i]);
    __syncthreads();

    float acc[2][4][4];
    #pragma unroll
    for (int i = 0; i < 2; i++)
        #pragma unroll
        for (int j = 0; j < 4; j++)
            #pragma unroll
            for (int r = 0; r < 4; r++) acc[i][j][r] = 0.f;

    int buf = 0;
    for (int k0 = 32; k0 < K; k0 += 32) {
        #pragma unroll
        for (int i = 0; i < 4; i++)
            abuf[i] = *(const float4*)&A[(size_t)(brow + a_r + i * 32) * K + k0 + a_c];
        #pragma unroll
        for (int i = 0; i < 2; i++)
            bbuf[i] = *(const float4*)&W[(size_t)(k0 + b_r + i * 16) * N + bcol + b_c];

        #pragma unroll
        for (int kk = 0; kk < 32; kk += 8) {
            float af[2][4];
            #pragma unroll
            for (int i = 0; i < 2; i++) {
                int mb = warp_m + i * 16;
                af[i][0] = As[buf][(mb + lg) * AS_STRIDE + kk + lt];
                af[i][1] = As[buf][(mb + 8 + lg) * AS_STRIDE + kk + lt];
                af[i][2] = As[buf][(mb + lg) * AS_STRIDE + kk + 4 + lt];
                af[i][3] = As[buf][(mb + 8 + lg) * AS_STRIDE + kk + 4 + lt];
            }
            float bf[4][2];
            #pragma unroll
            for (int j = 0; j < 4; j++) {
                int nb = warp_n + j * 8 + lg;
                bf[j][0] = Bs[buf][(kk + lt) * BS_STRIDE + nb];
                bf[j][1] = Bs[buf][(kk + 4 + lt) * BS_STRIDE + nb];
            }
            #pragma unroll
            for (int i = 0; i < 2; i++)
                #pragma unroll
                for (int j = 0; j < 4; j++)
                    mma_tf32(acc[i][j][0], acc[i][j][1], acc[i][j][2], acc[i][j][3],
                             af[i][0], af[i][1], af[i][2], af[i][3],
                             bf[j][0], bf[j][1]);
        }

        #pragma unroll
        for (int i = 0; i < 4; i++)
            *(float4*)&As[buf ^ 1][(a_r + i * 32) * AS_STRIDE + a_c] = tf32r4(abuf[i]);
        #pragma unroll
        for (int i = 0; i < 2; i++)
            *(float4*)&Bs[buf ^ 1][(b_r + i * 16) * BS_STRIDE + b_c] = tf32r4(bbuf[i]);
        __syncthreads();
        buf ^= 1;
    }

    #pragma unroll
    for (int kk = 0; kk < 32; kk += 8) {
        float af[2][4];
        #pragma unroll
        for (int i = 0; i < 2; i++) {
            int mb = warp_m + i * 16;
            af[i][0] = As[buf][(mb + lg) * AS_STRIDE + kk + lt];
            af[i][1] = As[buf][(mb + 8 + lg) * AS_STRIDE + kk + lt];
            af[i][2] = As[buf][(mb + lg) * AS_STRIDE + kk + 4 + lt];
            af[i][3] = As[buf][(mb + 8 + lg) * AS_STRIDE + kk + 4 + lt];
        }
        float bf[4][2];
        #pragma unroll
        for (int j = 0; j < 4; j++) {
            int nb = warp_n + j * 8 + lg;
            bf[j][0] = Bs[buf][(kk + lt) * BS_STRIDE + nb];
            bf[j][1] = Bs[buf][(kk + 4 + lt) * BS_STRIDE + nb];
        }
        #pragma unroll
        for (int i = 0; i < 2; i++)
            #pragma unroll
            for (int j = 0; j < 4; j++)
                mma_tf32(acc[i][j][0], acc[i][j][1], acc[i][j][2], acc[i][j][3],
                         af[i][0], af[i][1], af[i][2], af[i][3],
                         bf[j][0], bf[j][1]);
    }

    #pragma unroll
    for (int i = 0; i < 2; i++) {
        #pragma unroll
        for (int j = 0; j < 4; j++) {
            int col = bcol + warp_n + j * 8 + 2 * lt;
            float bx = bias[col], by = bias[col + 1];
            int r0 = brow + warp_m + i * 16 + lg;
            float2 v0 = make_float2(acc[i][j][0] + bx, acc[i][j][1] + by);
            float2 v1 = make_float2(acc[i][j][2] + bx, acc[i][j][3] + by);
            if (RELU) {
                v0.x = fmaxf(v0.x, 0.f); v0.y = fmaxf(v0.y, 0.f);
                v1.x = fmaxf(v1.x, 0.f); v1.y = fmaxf(v1.y, 0.f);
            }
            if (ROUND) {
                v0.x = tf32r(v0.x); v0.y = tf32r(v0.y);
                v1.x = tf32r(v1.x); v1.y = tf32r(v1.y);
            }
            *(float2*)&C[(size_t)r0 * N + col]       = v0;
            *(float2*)&C[(size_t)(r0 + 8) * N + col] = v1;
        }
    }
}

// =========================================================================
// Fused flash attention. Block: 128 q-rows of one (b,h). 8 warps, each warp
// owns 16 q-rows x all 64 kv-cols of the score tile. KV streamed in 64-row
// tiles, cp.async double buffered. q/k/v are pre-rounded to tf32 in gmem.
// =========================================================================
#define QS  68   // stride for Q/P/K tiles (  %32 == 4 -> conflict-free frags)
#define VS2 72   // stride for V tile      (  %32 == 8 -> conflict-free frags)
#define NKV (S_ / 64)

__global__ __launch_bounds__(256) void flash_kernel(
    const float* __restrict__ q, const float* __restrict__ k,
    const float* __restrict__ v, const float* __restrict__ mbias,
    float* __restrict__ out)
{
    extern __shared__ float sm[];
    float* QP = sm;                      // 128*QS  (Q tile, then P tiles)
    float* Ks = QP + 128 * QS;           // 2 * 64*QS
    float* Vs = Ks + 2 * 64 * QS;        // 2 * 64*VS2
    float* MB = Vs + 2 * 64 * VS2;       // 2 * 64

    int tid  = threadIdx.x;
    int lane = tid & 31;
    int warp = tid >> 5;
    int wm   = warp * 16;
    int lg = lane >> 2, lt = lane & 3;
    int brow = blockIdx.x * 128;
    int bh = blockIdx.y;
    int b = bh >> 3, h = bh & 7;

    const float* Qb  = q + (size_t)b * S_ * H_ + h * DH_;
    const float* Kb  = k + (size_t)b * S_ * H_ + h * DH_;
    const float* Vb  = v + (size_t)b * S_ * H_ + h * DH_;
    const float* MBg = mbias + b * S_;

    // ---- load Q tile (128x64) once; values already tf32 in gmem ----
    #pragma unroll
    for (int i = 0; i < 8; i++) {
        int f4 = tid + i * 256;          // 2048 float4
        int r = f4 >> 4, c = (f4 & 15) * 4;
        *(float4*)&QP[r * QS + c] = *(const float4*)&Qb[(size_t)(brow + r) * H_ + c];
    }
    __syncthreads();

    // Q fragments to registers: aq[kk][0..3] covers rows {wm+lg, wm+8+lg}
    float aq[8][4];
    #pragma unroll
    for (int kk = 0; kk < 8; kk++) {
        aq[kk][0] = QP[(wm + lg) * QS + kk * 8 + lt];
        aq[kk][1] = QP[(wm + 8 + lg) * QS + kk * 8 + lt];
        aq[kk][2] = QP[(wm + lg) * QS + kk * 8 + 4 + lt];
        aq[kk][3] = QP[(wm + 8 + lg) * QS + kk * 8 + 4 + lt];
    }
    __syncthreads();   // QP now reusable for P

    float acc_o[8][4];
    #pragma unroll
    for (int j = 0; j < 8; j++)
        #pragma unroll
        for (int r = 0; r < 4; r++) acc_o[j][r] = 0.f;
    float m0 = -1e30f, m1 = -1e30f, l0 = 0.f, l1 = 0.f;

    // kv tile loader (cp.async)
    auto load_kv = [&](int buf, int it) {
        int kv0 = it * 64;
        float* kd = Ks + buf * 64 * QS;
        float* vd = Vs + buf * 64 * VS2;
        #pragma unroll
        for (int i = 0; i < 4; i++) {
            int f4 = tid + i * 256;
            int r = f4 >> 4, c = (f4 & 15) * 4;
            cp_async16(&kd[r * QS + c],  &Kb[(size_t)(kv0 + r) * H_ + c]);
            cp_async16(&vd[r * VS2 + c], &Vb[(size_t)(kv0 + r) * H_ + c]);
        }
        if (tid < 16) cp_async16(&MB[buf * 64 + tid * 4], &MBg[kv0 + tid * 4]);
    };

    load_kv(0, 0);
    cp_commit();

    for (int it = 0; it < NKV; it++) {
        int buf = it & 1;
        if (it + 1 < NKV) {
            load_kv(buf ^ 1, it + 1);
            cp_commit();
            asm volatile("cp.async.wait_group 1;");
        } else {
            asm volatile("cp.async.wait_group 0;");
        }
        __syncthreads();

        const float* Kt  = Ks + buf * 64 * QS;
        const float* Vt  = Vs + buf * 64 * VS2;
        const float* MBt = MB + buf * 64;

        // ---- S = Q @ K^T (16x64 per warp) ----
        float accs[8][4];
        #pragma unroll
        for (int j = 0; j < 8; j++)
            #pragma unroll
            for (int r = 0; r < 4; r++) accs[j][r] = 0.f;
        #pragma unroll
        for (int kk = 0; kk < 8; kk++) {
            #pragma unroll
            for (int j = 0; j < 8; j++) {
                float b0 = Kt[(j * 8 + lg) * QS + kk * 8 + lt];
                float b1 = Kt[(j * 8 + lg) * QS + kk * 8 + 4 + lt];
                mma_tf32(accs[j][0], accs[j][1], accs[j][2], accs[j][3],
                         aq[kk][0], aq[kk][1], aq[kk][2], aq[kk][3], b0, b1);
            }
        }

        // ---- scale + mask bias, row max ----
        float mr0 = -1e30f, mr1 = -1e30f;
        #pragma unroll
        for (int j = 0; j < 8; j++) {
            float mb0 = MBt[j * 8 + 2 * lt];
            float mb1 = MBt[j * 8 + 2 * lt + 1];
            accs[j][0] = accs[j][0] * 0.125f + mb0;
            accs[j][1] = accs[j][1] * 0.125f + mb1;
            accs[j][2] = accs[j][2] * 0.125f + mb0;
            accs[j][3] = accs[j][3] * 0.125f + mb1;
            mr0 = fmaxf(mr0, fmaxf(accs[j][0], accs[j][1]));
            mr1 = fmaxf(mr1, fmaxf(accs[j][2], accs[j][3]));
        }
        mr0 = fmaxf(mr0, __shfl_xor_sync(0xffffffffu, mr0, 1));
        mr0 = fmaxf(mr0, __shfl_xor_sync(0xffffffffu, mr0, 2));
        mr1 = fmaxf(mr1, __shfl_xor_sync(0xffffffffu, mr1, 1));
        mr1 = fmaxf(mr1, __shfl_xor_sync(0xffffffffu, mr1, 2));

        float mn0 = fmaxf(m0, mr0), mn1 = fmaxf(m1, mr1);
        float al0 = __expf(m0 - mn0), al1 = __expf(m1 - mn1);
        m0 = mn0; m1 = mn1;

        // ---- P = exp(S - m), row sums, store P to smem (tf32) ----
        float ps0 = 0.f, ps1 = 0.f;
        #pragma unroll
        for (int j = 0; j < 8; j++) {
            float p0 = __expf(accs[j][0] - mn0);
            float p1 = __expf(accs[j][1] - mn0);
            float p2 = __expf(accs[j][2] - mn1);
            float p3 = __expf(accs[j][3] - mn1);
            ps0 += p0 + p1;
            ps1 += p2 + p3;
            int cb = j * 8 + 2 * lt;
            *(float2*)&QP[(wm + lg) * QS + cb]     = make_float2(tf32r(p0), tf32r(p1));
            *(float2*)&QP[(wm + 8 + lg) * QS + cb] = make_float2(tf32r(p2), tf32r(p3));
        }
        ps0 += __shfl_xor_sync(0xffffffffu, ps0, 1);
        ps0 += __shfl_xor_sync(0xffffffffu, ps0, 2);
        ps1 += __shfl_xor_sync(0xffffffffu, ps1, 1);
        ps1 += __shfl_xor_sync(0xffffffffu, ps1, 2);
        l0 = l0 * al0 + ps0;
        l1 = l1 * al1 + ps1;

        // rescale running output
        #pragma unroll
        for (int j = 0; j < 8; j++) {
            acc_o[j][0] *= al0; acc_o[j][1] *= al0;
            acc_o[j][2] *= al1; acc_o[j][3] *= al1;
        }
        __syncwarp();

        // ---- O += P @ V ----
        #pragma unroll
        for (int kk = 0; kk < 8; kk++) {
            float a0 = QP[(wm + lg) * QS + kk * 8 + lt];
            float a1 = QP[(wm + 8 + lg) * QS + kk * 8 + lt];
            float a2 = QP[(wm + lg) * QS + kk * 8 + 4 + lt];
            float a3 = QP[(wm + 8 + lg) * QS + kk * 8 + 4 + lt];
            #pragma unroll
            for (int j = 0; j < 8; j++) {
                float b0 = Vt[(kk * 8 + lt) * VS2 + j * 8 + lg];
                float b1 = Vt[(kk * 8 + 4 + lt) * VS2 + j * 8 + lg];
                mma_tf32(acc_o[j][0], acc_o[j][1], acc_o[j][2], acc_o[j][3],
                         a0, a1, a2, a3, b0, b1);
            }
        }
        __syncthreads();
    }

    // ---- epilogue: divide by l, write to out[tok][h*64+col] ----
    float i0 = 1.f / l0, i1 = 1.f / l1;
    int r0 = brow + wm + lg;
    int tok0 = b * S_ + r0;
    #pragma unroll
    for (int j = 0; j < 8; j++) {
        int col = h * DH_ + j * 8 + 2 * lt;
        *(float2*)&out[(size_t)tok0 * H_ + col] =
            make_float2(acc_o[j][0] * i0, acc_o[j][1] * i0);
        *(float2*)&out[(size_t)(tok0 + 8) * H_ + col] =
            make_float2(acc_o[j][2] * i1, acc_o[j][3] * i1);
    }
}

// ---------------- residual + LayerNorm ----------------
__global__ __launch_bounds__(256) void add_ln_kernel(
    const float* __restrict__ xin, const float* __restrict__ y,
    const float* __restrict__ gamma, const float* __restrict__ beta,
    float* __restrict__ out)
{
    int t = blockIdx.x;
    int tid = threadIdx.x;
    const float* yr = y + (size_t)t * H_;
    float v0 = yr[tid], v1 = yr[tid + 256];
    __shared__ float s1[256], s2[256];
    s1[tid] = v0 + v1;
    s2[tid] = v0 * v0 + v1 * v1;
    __syncthreads();
    for (int off = 128; off > 0; off >>= 1) {
        if (tid < off) { s1[tid] += s1[tid + off]; s2[tid] += s2[tid + off]; }
        __syncthreads();
    }
    float mean = s1[0] * (1.f / (float)H_);
    float var  = s2[0] * (1.f / (float)H_) - mean * mean;
    float r = rsqrtf(var + 1e-5f);
    size_t base = (size_t)t * H_;
    out[base + tid]       = xin[base + tid]       + (v0 - mean) * r * gamma[tid]       + beta[tid];
    out[base + tid + 256] = xin[base + tid + 256] + (v1 - mean) * r * gamma[tid + 256] + beta[tid + 256];
}

// ---------------- host launcher ----------------
extern "C" void kernel_launch(void* const* d_in, const int* in_sizes, int n_in,
                              void* d_out, int out_size)
{
    const int*   src  = (const int*)  d_in[0];
    const int*   mask = (const int*)  d_in[1];
    const float* emb  = (const float*)d_in[2];
    const float* Wq   = (const float*)d_in[3];
    const float* bq   = (const float*)d_in[4];
    const float* Wk   = (const float*)d_in[5];
    const float* bk   = (const float*)d_in[6];
    const float* Wv   = (const float*)d_in[7];
    const float* bv   = (const float*)d_in[8];
    const float* Wo   = (const float*)d_in[9];
    const float* bo   = (const float*)d_in[10];
    const float* gamma= (const float*)d_in[11];
    const float* beta = (const float*)d_in[12];
    const float* W1   = (const float*)d_in[13];
    const float* b1   = (const float*)d_in[14];
    const float* W2   = (const float*)d_in[15];
    const float* b2   = (const float*)d_in[16];

    float *x, *q, *k, *v, *t, *t2, *res, *h1, *mb;
    cudaGetSymbolAddress((void**)&x,   g_x);
    cudaGetSymbolAddress((void**)&q,   g_q);
    cudaGetSymbolAddress((void**)&k,   g_k);
    cudaGetSymbolAddress((void**)&v,   g_v);
    cudaGetSymbolAddress((void**)&t,   g_t);
    cudaGetSymbolAddress((void**)&t2,  g_t2);
    cudaGetSymbolAddress((void**)&res, g_res);
    cudaGetSymbolAddress((void**)&h1,  g_h1);
    cudaGetSymbolAddress((void**)&mb,  g_mb);

    const int FLASH_SMEM = (128 * QS + 2 * 64 * QS + 2 * 64 * VS2 + 2 * 64) * 4;
    cudaFuncSetAttribute(flash_kernel,
                         cudaFuncAttributeMaxDynamicSharedMemorySize, FLASH_SMEM);

    embed_kernel<<<(M_ * H_) / 256, 256>>>(src, emb, x);
    maskbias_kernel<<<(M_ + 255) / 256, 256>>>(mask, mb);

    dim3 gQKV (H_ / 64,  M_ / 128, 3);           // (8, 32, 3)
    dim3 gProj(H_ / 64,  M_ / 128, 1);           // (8, 32)
    dim3 gFfn1(FF_ / 64, M_ / 128, 1);           // (32, 32)
    dim3 gFlash(S_ / 128, B_ * NH_);             // (16, 16)

    for (int i = 0; i < L_; i++) {
        const float* Wq_i = Wq + (size_t)i * H_ * H_;
        const float* Wk_i = Wk + (size_t)i * H_ * H_;
        const float* Wv_i = Wv + (size_t)i * H_ * H_;
        const float* Wo_i = Wo + (size_t)i * H_ * H_;
        const float* W1_i = W1 + (size_t)i * H_ * FF_;
        const float* W2_i = W2 + (size_t)i * FF_ * H_;
        const float* bq_i = bq + i * H_;
        const float* bk_i = bk + i * H_;
        const float* bv_i = bv + i * H_;
        const float* bo_i = bo + i * H_;
        const float* b1_i = b1 + i * FF_;
        const float* b2_i = b2 + i * H_;
        const float* g_i  = gamma + i * H_;
        const float* be_i = beta  + i * H_;
        float* xout = (i == L_ - 1) ? (float*)d_out : x;

        // fused QKV projections, outputs tf32-rounded for flash
        gemm_tc_kernel<false, true><<<gQKV, 256>>>(x, Wq_i, Wk_i, Wv_i, bq_i, bk_i, bv_i,
                                                   q, k, v, M_, H_, H_);

        flash_kernel<<<gFlash, 256, FLASH_SMEM>>>(q, k, v, mb, t);

        gemm_tc_kernel<false, false><<<gProj, 256>>>(t, Wo_i, Wo_i, Wo_i, bo_i, bo_i, bo_i,
                                                     t2, t2, t2, M_, H_, H_);
        add_ln_kernel<<<M_, 256>>>(x, t2, g_i, be_i, res);

        gemm_tc_kernel<true, false><<<gFfn1, 256>>>(res, W1_i, W1_i, W1_i, b1_i, b1_i, b1_i,
                                                    h1, h1, h1, M_, FF_, H_);
        gemm_tc_kernel<false, false><<<gProj, 256>>>(h1, W2_i, W2_i, W2_i, b2_i, b2_i, b2_i,
                                                     t2, t2, t2, M_, H_, FF_);
        add_ln_kernel<<<M_, 256>>>(res, t2, g_i, be_i, xout);
    }
}

// round 5
// speedup vs baseline: 4.8271x; 1.0771x over previous
#include <cuda_runtime.h>
#include <cuda_bf16.h>
#include <math.h>

// Problem dims
#define B_  2
#define S_  2048
#define H_  512
#define NH_ 8
#define DH_ 64
#define L_  6
#define FF_ 2048          // 4*H
#define M_  (B_*S_)       // 4096 tokens

// ---------------- device scratch (no cudaMalloc allowed) ----------------
__device__ float g_x  [M_*H_];
__device__ float g_xr [M_*H_];       // tf32-rounded copy of x (GEMM A input)
__device__ float g_q  [M_*H_];
__device__ float g_k  [M_*H_];
__device__ float g_v  [M_*H_];
__device__ float g_t  [M_*H_];
__device__ float g_t2 [M_*H_];
__device__ float g_res[M_*H_];
__device__ float g_resr[M_*H_];      // rounded copy of res
__device__ float g_h1 [M_*FF_];
__device__ float g_mb [M_];          // mask bias: 0 or -1e20 per (b,s)
__device__ float g_wr [18874368];    // tf32-rounded weights [Wq|Wk|Wv|Wo|W1|W2]

#define WOFF_Q  0
#define WOFF_K  (L_*H_*H_)
#define WOFF_V  (2*L_*H_*H_)
#define WOFF_O  (3*L_*H_*H_)
#define WOFF_1  (4*L_*H_*H_)
#define WOFF_2  (4*L_*H_*H_ + L_*H_*FF_)

// ---------------- helpers ----------------
__device__ __forceinline__ float tf32r(float x) {
    float y;
    asm("cvt.rna.tf32.f32 %0, %1;" : "=f"(y) : "f"(x));
    return y;
}
__device__ __forceinline__ float4 tf32r4(float4 v) {
    v.x = tf32r(v.x); v.y = tf32r(v.y); v.z = tf32r(v.z); v.w = tf32r(v.w);
    return v;
}
__device__ __forceinline__ void mma_tf32(
    float& c0, float& c1, float& c2, float& c3,
    float a0, float a1, float a2, float a3, float b0, float b1)
{
    asm volatile(
        "mma.sync.aligned.m16n8k8.row.col.f32.tf32.tf32.f32 "
        "{%0,%1,%2,%3}, {%4,%5,%6,%7}, {%8,%9}, {%0,%1,%2,%3};\n"
        : "+f"(c0), "+f"(c1), "+f"(c2), "+f"(c3)
        : "r"(__float_as_uint(a0)), "r"(__float_as_uint(a1)),
          "r"(__float_as_uint(a2)), "r"(__float_as_uint(a3)),
          "r"(__float_as_uint(b0)), "r"(__float_as_uint(b1)));
}
__device__ __forceinline__ void cp_async16(float* dst, const float* src) {
    unsigned s = (unsigned)__cvta_generic_to_shared(dst);
    asm volatile("cp.async.cg.shared.global [%0], [%1], 16;" :: "r"(s), "l"(src));
}
__device__ __forceinline__ void cp_commit() {
    asm volatile("cp.async.commit_group;");
}

// ---------------- weight rounding ----------------
__global__ __launch_bounds__(256) void round_kernel(
    const float* __restrict__ src, float* __restrict__ dst)
{
    int i = blockIdx.x * 256 + threadIdx.x;
    *(float4*)&dst[i * 4] = tf32r4(*(const float4*)&src[i * 4]);
}

// ---------------- embedding + sinusoidal posenc ----------------
__global__ __launch_bounds__(256) void embed_kernel(
    const int* __restrict__ src, const float* __restrict__ emb,
    float* __restrict__ x, float* __restrict__ xr)
{
    int idx = blockIdx.x * 256 + threadIdx.x;
    int d   = idx & (H_ - 1);
    int tok = idx >> 9;
    int s   = tok & (S_ - 1);
    int j2  = (d >> 1) * 2;
    float div = powf(10000.0f, (float)j2 * (1.0f / (float)H_));
    float arg = (float)s / div;
    float pe  = (d & 1) ? cosf(arg) : sinf(arg);
    float v = emb[(size_t)src[tok] * H_ + d] + pe;
    x[idx]  = v;
    xr[idx] = tf32r(v);
}

__global__ __launch_bounds__(256) void maskbias_kernel(
    const int* __restrict__ mask, float* __restrict__ mb)
{
    int i = blockIdx.x * 256 + threadIdx.x;
    if (i < M_) mb[i] = mask[i] ? 0.f : -1e20f;
}

// =========================================================================
// 3-stage cp.async tf32 GEMM: C = A[M,K] @ W[K,N] + bias (+ReLU) (+round)
// BM=128 BN=128 BK=32, 256 thr = 8 warps (4x2), warp tile 32x64.
// A and W must be pre-rounded to tf32. No cvt in kernel.
// QKV fusion via blockIdx.z.
// =========================================================================
#define GAS 36     // As row stride (frag bank = 4lg+lt, conflict-free)
#define GBS 136    // Bs row stride (frag bank = 8lt+lg, conflict-free)
#define GEMM_SMEM ((3 * (128 * GAS + 32 * GBS)) * 4)

template<bool RELU, bool ROUND>
__global__ __launch_bounds__(256, 2) void gemm_tc_kernel(
    const float* __restrict__ A,
    const float* __restrict__ Wa, const float* __restrict__ Wb, const float* __restrict__ Wc,
    const float* __restrict__ ba, const float* __restrict__ bb, const float* __restrict__ bc,
    float* __restrict__ Ca, float* __restrict__ Cb_, float* __restrict__ Cc,
    int M, int N, int K)
{
    extern __shared__ float sm[];
    float* As = sm;                    // 3 stages of 128*GAS
    float* Bs = sm + 3 * 128 * GAS;    // 3 stages of 32*GBS

    int tid  = threadIdx.x;
    int lane = tid & 31;
    int warp = tid >> 5;
    int warp_m = (warp >> 1) * 32;
    int warp_n = (warp & 1) * 64;
    int brow = blockIdx.y * 128;
    int bcol = blockIdx.x * 128;
    int z = blockIdx.z;
    const float* W    = (z == 0) ? Wa : (z == 1) ? Wb : Wc;
    const float* bias = (z == 0) ? ba : (z == 1) ? bb : bc;
    float*       C    = (z == 0) ? Ca : (z == 1) ? Cb_ : Cc;

    int lg = lane >> 2, lt = lane & 3;

    // cp.async store mappings (conflict-free, fully-coalesced gmem)
    int a_row0 = warp * 4 + (lane >> 3);                 // + 32*i
    int a_col  = (((lane & 7) - (lane >> 3)) & 7) * 4;   // bank-spread chunk
    int b_row0 = tid >> 5;                               // + 8*i
    int b_col  = lane * 4;

    auto load_tile = [&](int st, int k0) {
        float* as = As + st * 128 * GAS;
        float* bs = Bs + st * 32 * GBS;
        #pragma unroll
        for (int i = 0; i < 4; i++) {
            int r = a_row0 + i * 32;
            cp_async16(&as[r * GAS + a_col], &A[(size_t)(brow + r) * K + k0 + a_col]);
        }
        #pragma unroll
        for (int i = 0; i < 4; i++) {
            int r = b_row0 + i * 8;
            cp_async16(&bs[r * GBS + b_col], &W[(size_t)(k0 + r) * N + bcol + b_col]);
        }
        cp_commit();
    };

    int nk = K / 32;
    load_tile(0, 0);
    load_tile(1, 32);

    float acc[2][8][4];
    #pragma unroll
    for (int i = 0; i < 2; i++)
        #pragma unroll
        for (int j = 0; j < 8; j++)
            #pragma unroll
            for (int r = 0; r < 4; r++) acc[i][j][r] = 0.f;

    for (int t = 0; t < nk; t++) {
        asm volatile("cp.async.wait_group 1;");
        __syncthreads();
        if (t + 2 < nk) load_tile((t + 2) % 3, (t + 2) * 32);
        else cp_commit();   // empty group keeps the wait count aligned

        const float* as = As + (t % 3) * 128 * GAS;
        const float* bs = Bs + (t % 3) * 32 * GBS;

        #pragma unroll
        for (int kk = 0; kk < 32; kk += 8) {
            float af[2][4];
            #pragma unroll
            for (int i = 0; i < 2; i++) {
                int mb = warp_m + i * 16;
                af[i][0] = as[(mb + lg) * GAS + kk + lt];
                af[i][1] = as[(mb + 8 + lg) * GAS + kk + lt];
                af[i][2] = as[(mb + lg) * GAS + kk + 4 + lt];
                af[i][3] = as[(mb + 8 + lg) * GAS + kk + 4 + lt];
            }
            float bf[8][2];
            #pragma unroll
            for (int j = 0; j < 8; j++) {
                int nb = warp_n + j * 8 + lg;
                bf[j][0] = bs[(kk + lt) * GBS + nb];
                bf[j][1] = bs[(kk + 4 + lt) * GBS + nb];
            }
            #pragma unroll
            for (int i = 0; i < 2; i++)
                #pragma unroll
                for (int j = 0; j < 8; j++)
                    mma_tf32(acc[i][j][0], acc[i][j][1], acc[i][j][2], acc[i][j][3],
                             af[i][0], af[i][1], af[i][2], af[i][3],
                             bf[j][0], bf[j][1]);
        }
        __syncthreads();
    }

    // epilogue
    #pragma unroll
    for (int i = 0; i < 2; i++) {
        #pragma unroll
        for (int j = 0; j < 8; j++) {
            int col = bcol + warp_n + j * 8 + 2 * lt;
            float bx = bias[col], by = bias[col + 1];
            int r0 = brow + warp_m + i * 16 + lg;
            float2 v0 = make_float2(acc[i][j][0] + bx, acc[i][j][1] + by);
            float2 v1 = make_float2(acc[i][j][2] + bx, acc[i][j][3] + by);
            if (RELU) {
                v0.x = fmaxf(v0.x, 0.f); v0.y = fmaxf(v0.y, 0.f);
                v1.x = fmaxf(v1.x, 0.f); v1.y = fmaxf(v1.y, 0.f);
            }
            if (ROUND) {
                v0.x = tf32r(v0.x); v0.y = tf32r(v0.y);
                v1.x = tf32r(v1.x); v1.y = tf32r(v1.y);
            }
            *(float2*)&C[(size_t)r0 * N + col]       = v0;
            *(float2*)&C[(size_t)(r0 + 8) * N + col] = v1;
        }
    }
}

// =========================================================================
// Fused flash attention (unchanged from R4 except tf32-rounded output).
// =========================================================================
#define QS  68
#define VS2 72
#define NKV (S_ / 64)

__global__ __launch_bounds__(256) void flash_kernel(
    const float* __restrict__ q, const float* __restrict__ k,
    const float* __restrict__ v, const float* __restrict__ mbias,
    float* __restrict__ out)
{
    extern __shared__ float sm[];
    float* QP = sm;
    float* Ks = QP + 128 * QS;
    float* Vs = Ks + 2 * 64 * QS;
    float* MB = Vs + 2 * 64 * VS2;

    int tid  = threadIdx.x;
    int lane = tid & 31;
    int warp = tid >> 5;
    int wm   = warp * 16;
    int lg = lane >> 2, lt = lane & 3;
    int brow = blockIdx.x * 128;
    int bh = blockIdx.y;
    int b = bh >> 3, h = bh & 7;

    const float* Qb  = q + (size_t)b * S_ * H_ + h * DH_;
    const float* Kb  = k + (size_t)b * S_ * H_ + h * DH_;
    const float* Vb  = v + (size_t)b * S_ * H_ + h * DH_;
    const float* MBg = mbias + b * S_;

    #pragma unroll
    for (int i = 0; i < 8; i++) {
        int f4 = tid + i * 256;
        int r = f4 >> 4, c = (f4 & 15) * 4;
        *(float4*)&QP[r * QS + c] = *(const float4*)&Qb[(size_t)(brow + r) * H_ + c];
    }
    __syncthreads();

    float aq[8][4];
    #pragma unroll
    for (int kk = 0; kk < 8; kk++) {
        aq[kk][0] = QP[(wm + lg) * QS + kk * 8 + lt];
        aq[kk][1] = QP[(wm + 8 + lg) * QS + kk * 8 + lt];
        aq[kk][2] = QP[(wm + lg) * QS + kk * 8 + 4 + lt];
        aq[kk][3] = QP[(wm + 8 + lg) * QS + kk * 8 + 4 + lt];
    }
    __syncthreads();

    float acc_o[8][4];
    #pragma unroll
    for (int j = 0; j < 8; j++)
        #pragma unroll
        for (int r = 0; r < 4; r++) acc_o[j][r] = 0.f;
    float m0 = -1e30f, m1 = -1e30f, l0 = 0.f, l1 = 0.f;

    auto load_kv = [&](int buf, int it) {
        int kv0 = it * 64;
        float* kd = Ks + buf * 64 * QS;
        float* vd = Vs + buf * 64 * VS2;
        #pragma unroll
        for (int i = 0; i < 4; i++) {
            int f4 = tid + i * 256;
            int r = f4 >> 4, c = (f4 & 15) * 4;
            cp_async16(&kd[r * QS + c],  &Kb[(size_t)(kv0 + r) * H_ + c]);
            cp_async16(&vd[r * VS2 + c], &Vb[(size_t)(kv0 + r) * H_ + c]);
        }
        if (tid < 16) cp_async16(&MB[buf * 64 + tid * 4], &MBg[kv0 + tid * 4]);
    };

    load_kv(0, 0);
    cp_commit();

    for (int it = 0; it < NKV; it++) {
        int buf = it & 1;
        if (it + 1 < NKV) {
            load_kv(buf ^ 1, it + 1);
            cp_commit();
            asm volatile("cp.async.wait_group 1;");
        } else {
            asm volatile("cp.async.wait_group 0;");
        }
        __syncthreads();

        const float* Kt  = Ks + buf * 64 * QS;
        const float* Vt  = Vs + buf * 64 * VS2;
        const float* MBt = MB + buf * 64;

        float accs[8][4];
        #pragma unroll
        for (int j = 0; j < 8; j++)
            #pragma unroll
            for (int r = 0; r < 4; r++) accs[j][r] = 0.f;
        #pragma unroll
        for (int kk = 0; kk < 8; kk++) {
            #pragma unroll
            for (int j = 0; j < 8; j++) {
                float b0 = Kt[(j * 8 + lg) * QS + kk * 8 + lt];
                float b1 = Kt[(j * 8 + lg) * QS + kk * 8 + 4 + lt];
                mma_tf32(accs[j][0], accs[j][1], accs[j][2], accs[j][3],
                         aq[kk][0], aq[kk][1], aq[kk][2], aq[kk][3], b0, b1);
            }
        }

        float mr0 = -1e30f, mr1 = -1e30f;
        #pragma unroll
        for (int j = 0; j < 8; j++) {
            float mb0 = MBt[j * 8 + 2 * lt];
            float mb1 = MBt[j * 8 + 2 * lt + 1];
            accs[j][0] = accs[j][0] * 0.125f + mb0;
            accs[j][1] = accs[j][1] * 0.125f + mb1;
            accs[j][2] = accs[j][2] * 0.125f + mb0;
            accs[j][3] = accs[j][3] * 0.125f + mb1;
            mr0 = fmaxf(mr0, fmaxf(accs[j][0], accs[j][1]));
            mr1 = fmaxf(mr1, fmaxf(accs[j][2], accs[j][3]));
        }
        mr0 = fmaxf(mr0, __shfl_xor_sync(0xffffffffu, mr0, 1));
        mr0 = fmaxf(mr0, __shfl_xor_sync(0xffffffffu, mr0, 2));
        mr1 = fmaxf(mr1, __shfl_xor_sync(0xffffffffu, mr1, 1));
        mr1 = fmaxf(mr1, __shfl_xor_sync(0xffffffffu, mr1, 2));

        float mn0 = fmaxf(m0, mr0), mn1 = fmaxf(m1, mr1);
        float al0 = __expf(m0 - mn0), al1 = __expf(m1 - mn1);
        m0 = mn0; m1 = mn1;

        float ps0 = 0.f, ps1 = 0.f;
        #pragma unroll
        for (int j = 0; j < 8; j++) {
            float p0 = __expf(accs[j][0] - mn0);
            float p1 = __expf(accs[j][1] - mn0);
            float p2 = __expf(accs[j][2] - mn1);
            float p3 = __expf(accs[j][3] - mn1);
            ps0 += p0 + p1;
            ps1 += p2 + p3;
            int cb = j * 8 + 2 * lt;
            *(float2*)&QP[(wm + lg) * QS + cb]     = make_float2(tf32r(p0), tf32r(p1));
            *(float2*)&QP[(wm + 8 + lg) * QS + cb] = make_float2(tf32r(p2), tf32r(p3));
        }
        ps0 += __shfl_xor_sync(0xffffffffu, ps0, 1);
        ps0 += __shfl_xor_sync(0xffffffffu, ps0, 2);
        ps1 += __shfl_xor_sync(0xffffffffu, ps1, 1);
        ps1 += __shfl_xor_sync(0xffffffffu, ps1, 2);
        l0 = l0 * al0 + ps0;
        l1 = l1 * al1 + ps1;

        #pragma unroll
        for (int j = 0; j < 8; j++) {
            acc_o[j][0] *= al0; acc_o[j][1] *= al0;
            acc_o[j][2] *= al1; acc_o[j][3] *= al1;
        }
        __syncwarp();

        #pragma unroll
        for (int kk = 0; kk < 8; kk++) {
            float a0 = QP[(wm + lg) * QS + kk * 8 + lt];
            float a1 = QP[(wm + 8 + lg) * QS + kk * 8 + lt];
            float a2 = QP[(wm + lg) * QS + kk * 8 + 4 + lt];
            float a3 = QP[(wm + 8 + lg) * QS + kk * 8 + 4 + lt];
            #pragma unroll
            for (int j = 0; j < 8; j++) {
                float b0 = Vt[(kk * 8 + lt) * VS2 + j * 8 + lg];
                float b1 = Vt[(kk * 8 + 4 + lt) * VS2 + j * 8 + lg];
                mma_tf32(acc_o[j][0], acc_o[j][1], acc_o[j][2], acc_o[j][3],
                         a0, a1, a2, a3, b0, b1);
            }
        }
        __syncthreads();
    }

    float i0 = 1.f / l0, i1 = 1.f / l1;
    int r0 = brow + wm + lg;
    int tok0 = b * S_ + r0;
    #pragma unroll
    for (int j = 0; j < 8; j++) {
        int col = h * DH_ + j * 8 + 2 * lt;
        *(float2*)&out[(size_t)tok0 * H_ + col] =
            make_float2(tf32r(acc_o[j][0] * i0), tf32r(acc_o[j][1] * i0));
        *(float2*)&out[(size_t)(tok0 + 8) * H_ + col] =
            make_float2(tf32r(acc_o[j][2] * i1), tf32r(acc_o[j][3] * i1));
    }
}

// ---------------- residual + LayerNorm, dual output (raw + rounded) ------
__global__ __launch_bounds__(256) void add_ln_kernel(
    const float* __restrict__ xin, const float* __restrict__ y,
    const float* __restrict__ gamma, const float* __restrict__ beta,
    float* __restrict__ out, float* __restrict__ out_r)
{
    int t = blockIdx.x;
    int tid = threadIdx.x;
    const float* yr = y + (size_t)t * H_;
    float v0 = yr[tid], v1 = yr[tid + 256];
    __shared__ float s1[256], s2[256];
    s1[tid] = v0 + v1;
    s2[tid] = v0 * v0 + v1 * v1;
    __syncthreads();
    for (int off = 128; off > 0; off >>= 1) {
        if (tid < off) { s1[tid] += s1[tid + off]; s2[tid] += s2[tid + off]; }
        __syncthreads();
    }
    float mean = s1[0] * (1.f / (float)H_);
    float var  = s2[0] * (1.f / (float)H_) - mean * mean;
    float r = rsqrtf(var + 1e-5f);
    size_t base = (size_t)t * H_;
    float o0 = xin[base + tid]       + (v0 - mean) * r * gamma[tid]       + beta[tid];
    float o1 = xin[base + tid + 256] + (v1 - mean) * r * gamma[tid + 256] + beta[tid + 256];
    out[base + tid]         = o0;
    out[base + tid + 256]   = o1;
    out_r[base + tid]       = tf32r(o0);
    out_r[base + tid + 256] = tf32r(o1);
}

// ---------------- host launcher ----------------
extern "C" void kernel_launch(void* const* d_in, const int* in_sizes, int n_in,
                              void* d_out, int out_size)
{
    const int*   src  = (const int*)  d_in[0];
    const int*   mask = (const int*)  d_in[1];
    const float* emb  = (const float*)d_in[2];
    const float* Wq   = (const float*)d_in[3];
    const float* bq   = (const float*)d_in[4];
    const float* Wk   = (const float*)d_in[5];
    const float* bk   = (const float*)d_in[6];
    const float* Wv   = (const float*)d_in[7];
    const float* bv   = (const float*)d_in[8];
    const float* Wo   = (const float*)d_in[9];
    const float* bo   = (const float*)d_in[10];
    const float* gamma= (const float*)d_in[11];
    const float* beta = (const float*)d_in[12];
    const float* W1   = (const float*)d_in[13];
    const float* b1   = (const float*)d_in[14];
    const float* W2   = (const float*)d_in[15];
    const float* b2   = (const float*)d_in[16];

    float *x, *xr, *q, *k, *v, *t, *t2, *res, *resr, *h1, *mb, *wr;
    cudaGetSymbolAddress((void**)&x,    g_x);
    cudaGetSymbolAddress((void**)&xr,   g_xr);
    cudaGetSymbolAddress((void**)&q,    g_q);
    cudaGetSymbolAddress((void**)&k,    g_k);
    cudaGetSymbolAddress((void**)&v,    g_v);
    cudaGetSymbolAddress((void**)&t,    g_t);
    cudaGetSymbolAddress((void**)&t2,   g_t2);
    cudaGetSymbolAddress((void**)&res,  g_res);
    cudaGetSymbolAddress((void**)&resr, g_resr);
    cudaGetSymbolAddress((void**)&h1,   g_h1);
    cudaGetSymbolAddress((void**)&mb,   g_mb);
    cudaGetSymbolAddress((void**)&wr,   g_wr);

    const int FLASH_SMEM = (128 * QS + 2 * 64 * QS + 2 * 64 * VS2 + 2 * 64) * 4;
    cudaFuncSetAttribute(flash_kernel,
                         cudaFuncAttributeMaxDynamicSharedMemorySize, FLASH_SMEM);
    cudaFuncSetAttribute(gemm_tc_kernel<false, true>,
                         cudaFuncAttributeMaxDynamicSharedMemorySize, GEMM_SMEM);
    cudaFuncSetAttribute(gemm_tc_kernel<false, false>,
                         cudaFuncAttributeMaxDynamicSharedMemorySize, GEMM_SMEM);
    cudaFuncSetAttribute(gemm_tc_kernel<true, true>,
                         cudaFuncAttributeMaxDynamicSharedMemorySize, GEMM_SMEM);

    // round weights into scratch (tf32)
    const int NQ = L_ * H_ * H_;       // 1572864
    round_kernel<<<NQ / 1024, 256>>>(Wq, wr + WOFF_Q);
    round_kernel<<<NQ / 1024, 256>>>(Wk, wr + WOFF_K);
    round_kernel<<<NQ / 1024, 256>>>(Wv, wr + WOFF_V);
    round_kernel<<<NQ / 1024, 256>>>(Wo, wr + WOFF_O);
    const int N1 = L_ * H_ * FF_;      // 6291456
    round_kernel<<<N1 / 1024, 256>>>(W1, wr + WOFF_1);
    round_kernel<<<N1 / 1024, 256>>>(W2, wr + WOFF_2);

    embed_kernel<<<(M_ * H_) / 256, 256>>>(src, emb, x, xr);
    maskbias_kernel<<<(M_ + 255) / 256, 256>>>(mask, mb);

    dim3 gQKV (H_ / 128,  M_ / 128, 3);          // (4, 32, 3)
    dim3 gProj(H_ / 128,  M_ / 128, 1);          // (4, 32)
    dim3 gFfn1(FF_ / 128, M_ / 128, 1);          // (16, 32)
    dim3 gFlash(S_ / 128, B_ * NH_);             // (16, 16)

    for (int i = 0; i < L_; i++) {
        const float* Wq_i = wr + WOFF_Q + (size_t)i * H_ * H_;
        const float* Wk_i = wr + WOFF_K + (size_t)i * H_ * H_;
        const float* Wv_i = wr + WOFF_V + (size_t)i * H_ * H_;
        const float* Wo_i = wr + WOFF_O + (size_t)i * H_ * H_;
        const float* W1_i = wr + WOFF_1 + (size_t)i * H_ * FF_;
        const float* W2_i = wr + WOFF_2 + (size_t)i * FF_ * H_;
        const float* bq_i = bq + i * H_;
        const float* bk_i = bk + i * H_;
        const float* bv_i = bv + i * H_;
        const float* bo_i = bo + i * H_;
        const float* b1_i = b1 + i * FF_;
        const float* b2_i = b2 + i * H_;
        const float* g_i  = gamma + i * H_;
        const float* be_i = beta  + i * H_;
        float* xout = (i == L_ - 1) ? (float*)d_out : x;

        // fused QKV projections (A = rounded x), outputs rounded for flash
        gemm_tc_kernel<false, true><<<gQKV, 256, GEMM_SMEM>>>(
            xr, Wq_i, Wk_i, Wv_i, bq_i, bk_i, bv_i, q, k, v, M_, H_, H_);

        flash_kernel<<<gFlash, 256, FLASH_SMEM>>>(q, k, v, mb, t);

        gemm_tc_kernel<false, false><<<gProj, 256, GEMM_SMEM>>>(
            t, Wo_i, Wo_i, Wo_i, bo_i, bo_i, bo_i, t2, t2, t2, M_, H_, H_);
        add_ln_kernel<<<M_, 256>>>(x, t2, g_i, be_i, res, resr);

        gemm_tc_kernel<true, true><<<gFfn1, 256, GEMM_SMEM>>>(
            resr, W1_i, W1_i, W1_i, b1_i, b1_i, b1_i, h1, h1, h1, M_, FF_, H_);
        gemm_tc_kernel<false, false><<<gProj, 256, GEMM_SMEM>>>(
            h1, W2_i, W2_i, W2_i, b2_i, b2_i, b2_i, t2, t2, t2, M_, H_, FF_);
        add_ln_kernel<<<M_, 256>>>(res, t2, g_i, be_i, xout, xr);
    }
}

// round 6
// speedup vs baseline: 4.8842x; 1.0118x over previous
#include <cuda_runtime.h>
#include <cuda_bf16.h>
#include <math.h>

// Problem dims
#define B_  2
#define S_  2048
#define H_  512
#define NH_ 8
#define DH_ 64
#define L_  6
#define FF_ 2048          // 4*H
#define M_  (B_*S_)       // 4096 tokens

// ---------------- device scratch (no cudaMalloc allowed) ----------------
__device__ float g_x  [M_*H_];
__device__ float g_xr [M_*H_];       // tf32-rounded copy of x (GEMM A input)
__device__ float g_q  [M_*H_];
__device__ float g_k  [M_*H_];
__device__ float g_v  [M_*H_];
__device__ float g_t  [M_*H_];
__device__ float g_t2a[M_*H_];
__device__ float g_t2b[M_*H_];
__device__ float g_res[M_*H_];
__device__ float g_resr[M_*H_];      // rounded copy of res
__device__ float g_h1 [M_*FF_];
__device__ float g_mb [M_];          // mask bias: 0 or -1e20 per (b,s)
__device__ float g_wr [18874368];    // tf32-rounded weights [Wq|Wk|Wv|Wo|W1|W2]

#define WOFF_Q  0
#define WOFF_K  (L_*H_*H_)
#define WOFF_V  (2*L_*H_*H_)
#define WOFF_O  (3*L_*H_*H_)
#define WOFF_1  (4*L_*H_*H_)
#define WOFF_2  (4*L_*H_*H_ + L_*H_*FF_)

// ---------------- helpers ----------------
__device__ __forceinline__ float tf32r(float x) {
    float y;
    asm("cvt.rna.tf32.f32 %0, %1;" : "=f"(y) : "f"(x));
    return y;
}
__device__ __forceinline__ float4 tf32r4(float4 v) {
    v.x = tf32r(v.x); v.y = tf32r(v.y); v.z = tf32r(v.z); v.w = tf32r(v.w);
    return v;
}
__device__ __forceinline__ void mma_tf32(
    float& c0, float& c1, float& c2, float& c3,
    float a0, float a1, float a2, float a3, float b0, float b1)
{
    asm volatile(
        "mma.sync.aligned.m16n8k8.row.col.f32.tf32.tf32.f32 "
        "{%0,%1,%2,%3}, {%4,%5,%6,%7}, {%8,%9}, {%0,%1,%2,%3};\n"
        : "+f"(c0), "+f"(c1), "+f"(c2), "+f"(c3)
        : "r"(__float_as_uint(a0)), "r"(__float_as_uint(a1)),
          "r"(__float_as_uint(a2)), "r"(__float_as_uint(a3)),
          "r"(__float_as_uint(b0)), "r"(__float_as_uint(b1)));
}
__device__ __forceinline__ void cp_async16(float* dst, const float* src) {
    unsigned s = (unsigned)__cvta_generic_to_shared(dst);
    asm volatile("cp.async.cg.shared.global [%0], [%1], 16;" :: "r"(s), "l"(src));
}
__device__ __forceinline__ void cp_commit() {
    asm volatile("cp.async.commit_group;");
}

// ---------------- weight rounding: all 6 tensors in one launch ----------------
#define RQ_ (L_*H_*H_/4)     // f4 count per H*H weight set: 393216
#define R1_ (L_*H_*FF_/4)    // 1572864
__global__ __launch_bounds__(256) void round_all_kernel(
    const float* __restrict__ Wq, const float* __restrict__ Wk,
    const float* __restrict__ Wv, const float* __restrict__ Wo,
    const float* __restrict__ W1, const float* __restrict__ W2,
    float* __restrict__ dst)
{
    long i = (long)blockIdx.x * 256 + threadIdx.x;   // f4 index into dst
    const float* src;
    long local;
    if (i < 4L * RQ_) {
        int region = (int)(i / RQ_);
        local = i - (long)region * RQ_;
        src = (region == 0) ? Wq : (region == 1) ? Wk : (region == 2) ? Wv : Wo;
    } else if (i < 4L * RQ_ + R1_) {
        local = i - 4L * RQ_;
        src = W1;
    } else {
        local = i - 4L * RQ_ - R1_;
        src = W2;
    }
    *(float4*)&dst[i * 4] = tf32r4(*(const float4*)&src[local * 4]);
}

// ---------------- embedding + sinusoidal posenc ----------------
__global__ __launch_bounds__(256) void embed_kernel(
    const int* __restrict__ src, const float* __restrict__ emb,
    float* __restrict__ x, float* __restrict__ xr)
{
    int idx = blockIdx.x * 256 + threadIdx.x;
    int d   = idx & (H_ - 1);
    int tok = idx >> 9;
    int s   = tok & (S_ - 1);
    int j2  = (d >> 1) * 2;
    float div = powf(10000.0f, (float)j2 * (1.0f / (float)H_));
    float arg = (float)s / div;
    float pe  = (d & 1) ? cosf(arg) : sinf(arg);
    float v = emb[(size_t)src[tok] * H_ + d] + pe;
    x[idx]  = v;
    xr[idx] = tf32r(v);
}

__global__ __launch_bounds__(256) void maskbias_kernel(
    const int* __restrict__ mask, float* __restrict__ mb)
{
    int i = blockIdx.x * 256 + threadIdx.x;
    if (i < M_) mb[i] = mask[i] ? 0.f : -1e20f;
}

// =========================================================================
// 3-stage cp.async tf32 GEMM core.  BM=128 BN=128 BK=32, 8 warps (4x2),
// warp tile 32x64.  A and W pre-rounded tf32.  Two front-ends:
//   gemm_tc_kernel : full-K, z selects one of 3 fused (W,bias,C) sets
//   gemm_tc_sk     : split-K (z = K-half), bias on z==0 only, C0/C1 outputs
// =========================================================================
#define GAS 36
#define GBS 136
#define GEMM_SMEM ((3 * (128 * GAS + 32 * GBS)) * 4)

template<bool RELU, bool ROUND>
__device__ __forceinline__ void gemm_core(
    const float* __restrict__ A, const float* __restrict__ W,
    const float* __restrict__ bias, float biasScale, float* __restrict__ C,
    int brow, int bcol, int N, int Kfull, int koff, int Kspan)
{
    extern __shared__ float sm[];
    float* As = sm;
    float* Bs = sm + 3 * 128 * GAS;

    int tid  = threadIdx.x;
    int lane = tid & 31;
    int warp = tid >> 5;
    int warp_m = (warp >> 1) * 32;
    int warp_n = (warp & 1) * 64;
    int lg = lane >> 2, lt = lane & 3;

    int a_row0 = warp * 4 + (lane >> 3);
    int a_col  = (((lane & 7) - (lane >> 3)) & 7) * 4;
    int b_row0 = tid >> 5;
    int b_col  = lane * 4;

    auto load_tile = [&](int st, int k0) {
        float* as = As + st * 128 * GAS;
        float* bs = Bs + st * 32 * GBS;
        #pragma unroll
        for (int i = 0; i < 4; i++) {
            int r = a_row0 + i * 32;
            cp_async16(&as[r * GAS + a_col], &A[(size_t)(brow + r) * Kfull + koff + k0 + a_col]);
        }
        #pragma unroll
        for (int i = 0; i < 4; i++) {
            int r = b_row0 + i * 8;
            cp_async16(&bs[r * GBS + b_col], &W[(size_t)(koff + k0 + r) * N + bcol + b_col]);
        }
        cp_commit();
    };

    int nk = Kspan / 32;
    load_tile(0, 0);
    load_tile(1, 32);

    float acc[2][8][4];
    #pragma unroll
    for (int i = 0; i < 2; i++)
        #pragma unroll
        for (int j = 0; j < 8; j++)
            #pragma unroll
            for (int r = 0; r < 4; r++) acc[i][j][r] = 0.f;

    for (int t = 0; t < nk; t++) {
        asm volatile("cp.async.wait_group 1;");
        __syncthreads();
        if (t + 2 < nk) load_tile((t + 2) % 3, (t + 2) * 32);
        else cp_commit();

        const float* as = As + (t % 3) * 128 * GAS;
        const float* bs = Bs + (t % 3) * 32 * GBS;

        #pragma unroll
        for (int kk = 0; kk < 32; kk += 8) {
            float af[2][4];
            #pragma unroll
            for (int i = 0; i < 2; i++) {
                int mb = warp_m + i * 16;
                af[i][0] = as[(mb + lg) * GAS + kk + lt];
                af[i][1] = as[(mb + 8 + lg) * GAS + kk + lt];
                af[i][2] = as[(mb + lg) * GAS + kk + 4 + lt];
                af[i][3] = as[(mb + 8 + lg) * GAS + kk + 4 + lt];
            }
            float bf[8][2];
            #pragma unroll
            for (int j = 0; j < 8; j++) {
                int nb = warp_n + j * 8 + lg;
                bf[j][0] = bs[(kk + lt) * GBS + nb];
                bf[j][1] = bs[(kk + 4 + lt) * GBS + nb];
            }
            #pragma unroll
            for (int i = 0; i < 2; i++)
                #pragma unroll
                for (int j = 0; j < 8; j++)
                    mma_tf32(acc[i][j][0], acc[i][j][1], acc[i][j][2], acc[i][j][3],
                             af[i][0], af[i][1], af[i][2], af[i][3],
                             bf[j][0], bf[j][1]);
        }
        __syncthreads();
    }

    #pragma unroll
    for (int i = 0; i < 2; i++) {
        #pragma unroll
        for (int j = 0; j < 8; j++) {
            int col = bcol + warp_n + j * 8 + 2 * lt;
            float bx = bias[col] * biasScale, by = bias[col + 1] * biasScale;
            int r0 = brow + warp_m + i * 16 + lg;
            float2 v0 = make_float2(acc[i][j][0] + bx, acc[i][j][1] + by);
            float2 v1 = make_float2(acc[i][j][2] + bx, acc[i][j][3] + by);
            if (RELU) {
                v0.x = fmaxf(v0.x, 0.f); v0.y = fmaxf(v0.y, 0.f);
                v1.x = fmaxf(v1.x, 0.f); v1.y = fmaxf(v1.y, 0.f);
            }
            if (ROUND) {
                v0.x = tf32r(v0.x); v0.y = tf32r(v0.y);
                v1.x = tf32r(v1.x); v1.y = tf32r(v1.y);
            }
            *(float2*)&C[(size_t)r0 * N + col]       = v0;
            *(float2*)&C[(size_t)(r0 + 8) * N + col] = v1;
        }
    }
}

template<bool RELU, bool ROUND>
__global__ __launch_bounds__(256, 2) void gemm_tc_kernel(
    const float* __restrict__ A,
    const float* __restrict__ Wa, const float* __restrict__ Wb, const float* __restrict__ Wc,
    const float* __restrict__ ba, const float* __restrict__ bb, const float* __restrict__ bc,
    float* __restrict__ Ca, float* __restrict__ Cb_, float* __restrict__ Cc,
    int M, int N, int K)
{
    int z = blockIdx.z;
    const float* W    = (z == 0) ? Wa : (z == 1) ? Wb : Wc;
    const float* bias = (z == 0) ? ba : (z == 1) ? bb : bc;
    float*       C    = (z == 0) ? Ca : (z == 1) ? Cb_ : Cc;
    gemm_core<RELU, ROUND>(A, W, bias, 1.f, C,
                           blockIdx.y * 128, blockIdx.x * 128, N, K, 0, K);
}

// split-K=2: z selects K-half; bias only on z==0; no relu/round (LN consumes)
__global__ __launch_bounds__(256, 2) void gemm_tc_sk(
    const float* __restrict__ A, const float* __restrict__ W,
    const float* __restrict__ bias,
    float* __restrict__ C0, float* __restrict__ C1,
    int M, int N, int K)
{
    int z = blockIdx.z;
    int Kh = K >> 1;
    gemm_core<false, false>(A, W, bias, z == 0 ? 1.f : 0.f,
                            z == 0 ? C0 : C1,
                            blockIdx.y * 128, blockIdx.x * 128, N, K, z * Kh, Kh);
}

// =========================================================================
// Fused flash attention (same as R5).
// =========================================================================
#define QS  68
#define VS2 72
#define NKV (S_ / 64)

__global__ __launch_bounds__(256) void flash_kernel(
    const float* __restrict__ q, const float* __restrict__ k,
    const float* __restrict__ v, const float* __restrict__ mbias,
    float* __restrict__ out)
{
    extern __shared__ float sm[];
    float* QP = sm;
    float* Ks = QP + 128 * QS;
    float* Vs = Ks + 2 * 64 * QS;
    float* MB = Vs + 2 * 64 * VS2;

    int tid  = threadIdx.x;
    int lane = tid & 31;
    int warp = tid >> 5;
    int wm   = warp * 16;
    int lg = lane >> 2, lt = lane & 3;
    int brow = blockIdx.x * 128;
    int bh = blockIdx.y;
    int b = bh >> 3, h = bh & 7;

    const float* Qb  = q + (size_t)b * S_ * H_ + h * DH_;
    const float* Kb  = k + (size_t)b * S_ * H_ + h * DH_;
    const float* Vb  = v + (size_t)b * S_ * H_ + h * DH_;
    const float* MBg = mbias + b * S_;

    #pragma unroll
    for (int i = 0; i < 8; i++) {
        int f4 = tid + i * 256;
        int r = f4 >> 4, c = (f4 & 15) * 4;
        *(float4*)&QP[r * QS + c] = *(const float4*)&Qb[(size_t)(brow + r) * H_ + c];
    }
    __syncthreads();

    float aq[8][4];
    #pragma unroll
    for (int kk = 0; kk < 8; kk++) {
        aq[kk][0] = QP[(wm + lg) * QS + kk * 8 + lt];
        aq[kk][1] = QP[(wm + 8 + lg) * QS + kk * 8 + lt];
        aq[kk][2] = QP[(wm + lg) * QS + kk * 8 + 4 + lt];
        aq[kk][3] = QP[(wm + 8 + lg) * QS + kk * 8 + 4 + lt];
    }
    __syncthreads();

    float acc_o[8][4];
    #pragma unroll
    for (int j = 0; j < 8; j++)
        #pragma unroll
        for (int r = 0; r < 4; r++) acc_o[j][r] = 0.f;
    float m0 = -1e30f, m1 = -1e30f, l0 = 0.f, l1 = 0.f;

    auto load_kv = [&](int buf, int it) {
        int kv0 = it * 64;
        float* kd = Ks + buf * 64 * QS;
        float* vd = Vs + buf * 64 * VS2;
        #pragma unroll
        for (int i = 0; i < 4; i++) {
            int f4 = tid + i * 256;
            int r = f4 >> 4, c = (f4 & 15) * 4;
            cp_async16(&kd[r * QS + c],  &Kb[(size_t)(kv0 + r) * H_ + c]);
            cp_async16(&vd[r * VS2 + c], &Vb[(size_t)(kv0 + r) * H_ + c]);
        }
        if (tid < 16) cp_async16(&MB[buf * 64 + tid * 4], &MBg[kv0 + tid * 4]);
    };

    load_kv(0, 0);
    cp_commit();

    for (int it = 0; it < NKV; it++) {
        int buf = it & 1;
        if (it + 1 < NKV) {
            load_kv(buf ^ 1, it + 1);
            cp_commit();
            asm volatile("cp.async.wait_group 1;");
        } else {
            asm volatile("cp.async.wait_group 0;");
        }
        __syncthreads();

        const float* Kt  = Ks + buf * 64 * QS;
        const float* Vt  = Vs + buf * 64 * VS2;
        const float* MBt = MB + buf * 64;

        float accs[8][4];
        #pragma unroll
        for (int j = 0; j < 8; j++)
            #pragma unroll
            for (int r = 0; r < 4; r++) accs[j][r] = 0.f;
        #pragma unroll
        for (int kk = 0; kk < 8; kk++) {
            #pragma unroll
            for (int j = 0; j < 8; j++) {
                float b0 = Kt[(j * 8 + lg) * QS + kk * 8 + lt];
                float b1 = Kt[(j * 8 + lg) * QS + kk * 8 + 4 + lt];
                mma_tf32(accs[j][0], accs[j][1], accs[j][2], accs[j][3],
                         aq[kk][0], aq[kk][1], aq[kk][2], aq[kk][3], b0, b1);
            }
        }

        float mr0 = -1e30f, mr1 = -1e30f;
        #pragma unroll
        for (int j = 0; j < 8; j++) {
            float mb0 = MBt[j * 8 + 2 * lt];
            float mb1 = MBt[j * 8 + 2 * lt + 1];
            accs[j][0] = accs[j][0] * 0.125f + mb0;
            accs[j][1] = accs[j][1] * 0.125f + mb1;
            accs[j][2] = accs[j][2] * 0.125f + mb0;
            accs[j][3] = accs[j][3] * 0.125f + mb1;
            mr0 = fmaxf(mr0, fmaxf(accs[j][0], accs[j][1]));
            mr1 = fmaxf(mr1, fmaxf(accs[j][2], accs[j][3]));
        }
        mr0 = fmaxf(mr0, __shfl_xor_sync(0xffffffffu, mr0, 1));
        mr0 = fmaxf(mr0, __shfl_xor_sync(0xffffffffu, mr0, 2));
        mr1 = fmaxf(mr1, __shfl_xor_sync(0xffffffffu, mr1, 1));
        mr1 = fmaxf(mr1, __shfl_xor_sync(0xffffffffu, mr1, 2));

        float mn0 = fmaxf(m0, mr0), mn1 = fmaxf(m1, mr1);
        float al0 = __expf(m0 - mn0), al1 = __expf(m1 - mn1);
        m0 = mn0; m1 = mn1;

        float ps0 = 0.f, ps1 = 0.f;
        #pragma unroll
        for (int j = 0; j < 8; j++) {
            float p0 = __expf(accs[j][0] - mn0);
            float p1 = __expf(accs[j][1] - mn0);
            float p2 = __expf(accs[j][2] - mn1);
            float p3 = __expf(accs[j][3] - mn1);
            ps0 += p0 + p1;
            ps1 += p2 + p3;
            int cb = j * 8 + 2 * lt;
            *(float2*)&QP[(wm + lg) * QS + cb]     = make_float2(tf32r(p0), tf32r(p1));
            *(float2*)&QP[(wm + 8 + lg) * QS + cb] = make_float2(tf32r(p2), tf32r(p3));
        }
        ps0 += __shfl_xor_sync(0xffffffffu, ps0, 1);
        ps0 += __shfl_xor_sync(0xffffffffu, ps0, 2);
        ps1 += __shfl_xor_sync(0xffffffffu, ps1, 1);
        ps1 += __shfl_xor_sync(0xffffffffu, ps1, 2);
        l0 = l0 * al0 + ps0;
        l1 = l1 * al1 + ps1;

        #pragma unroll
        for (int j = 0; j < 8; j++) {
            acc_o[j][0] *= al0; acc_o[j][1] *= al0;
            acc_o[j][2] *= al1; acc_o[j][3] *= al1;
        }
        __syncwarp();

        #pragma unroll
        for (int kk = 0; kk < 8; kk++) {
            float a0 = QP[(wm + lg) * QS + kk * 8 + lt];
            float a1 = QP[(wm + 8 + lg) * QS + kk * 8 + lt];
            float a2 = QP[(wm + lg) * QS + kk * 8 + 4 + lt];
            float a3 = QP[(wm + 8 + lg) * QS + kk * 8 + 4 + lt];
            #pragma unroll
            for (int j = 0; j < 8; j++) {
                float b0 = Vt[(kk * 8 + lt) * VS2 + j * 8 + lg];
                float b1 = Vt[(kk * 8 + 4 + lt) * VS2 + j * 8 + lg];
                mma_tf32(acc_o[j][0], acc_o[j][1], acc_o[j][2], acc_o[j][3],
                         a0, a1, a2, a3, b0, b1);
            }
        }
        __syncthreads();
    }

    float i0 = 1.f / l0, i1 = 1.f / l1;
    int r0 = brow + wm + lg;
    int tok0 = b * S_ + r0;
    #pragma unroll
    for (int j = 0; j < 8; j++) {
        int col = h * DH_ + j * 8 + 2 * lt;
        *(float2*)&out[(size_t)tok0 * H_ + col] =
            make_float2(tf32r(acc_o[j][0] * i0), tf32r(acc_o[j][1] * i0));
        *(float2*)&out[(size_t)(tok0 + 8) * H_ + col] =
            make_float2(tf32r(acc_o[j][2] * i1), tf32r(acc_o[j][3] * i1));
    }
}

// ------- residual + LayerNorm over (ya+yb), dual output (raw + rounded) ----
__global__ __launch_bounds__(256) void add_ln_kernel(
    const float* __restrict__ xin,
    const float* __restrict__ ya, const float* __restrict__ yb,
    const float* __restrict__ gamma, const float* __restrict__ beta,
    float* __restrict__ out, float* __restrict__ out_r)
{
    int t = blockIdx.x;
    int tid = threadIdx.x;
    size_t base = (size_t)t * H_;
    float v0 = ya[base + tid]       + yb[base + tid];
    float v1 = ya[base + tid + 256] + yb[base + tid + 256];
    __shared__ float s1[256], s2[256];
    s1[tid] = v0 + v1;
    s2[tid] = v0 * v0 + v1 * v1;
    __syncthreads();
    for (int off = 128; off > 0; off >>= 1) {
        if (tid < off) { s1[tid] += s1[tid + off]; s2[tid] += s2[tid + off]; }
        __syncthreads();
    }
    float mean = s1[0] * (1.f / (float)H_);
    float var  = s2[0] * (1.f / (float)H_) - mean * mean;
    float r = rsqrtf(var + 1e-5f);
    float o0 = xin[base + tid]       + (v0 - mean) * r * gamma[tid]       + beta[tid];
    float o1 = xin[base + tid + 256] + (v1 - mean) * r * gamma[tid + 256] + beta[tid + 256];
    out[base + tid]         = o0;
    out[base + tid + 256]   = o1;
    out_r[base + tid]       = tf32r(o0);
    out_r[base + tid + 256] = tf32r(o1);
}

// ---------------- host launcher ----------------
extern "C" void kernel_launch(void* const* d_in, const int* in_sizes, int n_in,
                              void* d_out, int out_size)
{
    const int*   src  = (const int*)  d_in[0];
    const int*   mask = (const int*)  d_in[1];
    const float* emb  = (const float*)d_in[2];
    const float* Wq   = (const float*)d_in[3];
    const float* bq   = (const float*)d_in[4];
    const float* Wk   = (const float*)d_in[5];
    const float* bk   = (const float*)d_in[6];
    const float* Wv   = (const float*)d_in[7];
    const float* bv   = (const float*)d_in[8];
    const float* Wo   = (const float*)d_in[9];
    const float* bo   = (const float*)d_in[10];
    const float* gamma= (const float*)d_in[11];
    const float* beta = (const float*)d_in[12];
    const float* W1   = (const float*)d_in[13];
    const float* b1   = (const float*)d_in[14];
    const float* W2   = (const float*)d_in[15];
    const float* b2   = (const float*)d_in[16];

    float *x, *xr, *q, *k, *v, *t, *t2a, *t2b, *res, *resr, *h1, *mb, *wr;
    cudaGetSymbolAddress((void**)&x,    g_x);
    cudaGetSymbolAddress((void**)&xr,   g_xr);
    cudaGetSymbolAddress((void**)&q,    g_q);
    cudaGetSymbolAddress((void**)&k,    g_k);
    cudaGetSymbolAddress((void**)&v,    g_v);
    cudaGetSymbolAddress((void**)&t,    g_t);
    cudaGetSymbolAddress((void**)&t2a,  g_t2a);
    cudaGetSymbolAddress((void**)&t2b,  g_t2b);
    cudaGetSymbolAddress((void**)&res,  g_res);
    cudaGetSymbolAddress((void**)&resr, g_resr);
    cudaGetSymbolAddress((void**)&h1,   g_h1);
    cudaGetSymbolAddress((void**)&mb,   g_mb);
    cudaGetSymbolAddress((void**)&wr,   g_wr);

    const int FLASH_SMEM = (128 * QS + 2 * 64 * QS + 2 * 64 * VS2 + 2 * 64) * 4;
    cudaFuncSetAttribute(flash_kernel,
                         cudaFuncAttributeMaxDynamicSharedMemorySize, FLASH_SMEM);
    cudaFuncSetAttribute(gemm_tc_kernel<false, true>,
                         cudaFuncAttributeMaxDynamicSharedMemorySize, GEMM_SMEM);
    cudaFuncSetAttribute(gemm_tc_kernel<true, true>,
                         cudaFuncAttributeMaxDynamicSharedMemorySize, GEMM_SMEM);
    cudaFuncSetAttribute(gemm_tc_sk,
                         cudaFuncAttributeMaxDynamicSharedMemorySize, GEMM_SMEM);

    // round all weights in one launch
    round_all_kernel<<<(4 * RQ_ + 2 * R1_) / 256, 256>>>(Wq, Wk, Wv, Wo, W1, W2, wr);

    embed_kernel<<<(M_ * H_) / 256, 256>>>(src, emb, x, xr);
    maskbias_kernel<<<(M_ + 255) / 256, 256>>>(mask, mb);

    dim3 gQKV (H_ / 128,  M_ / 128, 3);          // (4, 32, 3) = 384
    dim3 gSK  (H_ / 128,  M_ / 128, 2);          // (4, 32, 2) = 256 (split-K)
    dim3 gFfn1(FF_ / 128, M_ / 128, 1);          // (16, 32)   = 512
    dim3 gFlash(S_ / 128, B_ * NH_);             // (16, 16)   = 256

    for (int i = 0; i < L_; i++) {
        const float* Wq_i = wr + WOFF_Q + (size_t)i * H_ * H_;
        const float* Wk_i = wr + WOFF_K + (size_t)i * H_ * H_;
        const float* Wv_i = wr + WOFF_V + (size_t)i * H_ * H_;
        const float* Wo_i = wr + WOFF_O + (size_t)i * H_ * H_;
        const float* W1_i = wr + WOFF_1 + (size_t)i * H_ * FF_;
        const float* W2_i = wr + WOFF_2 + (size_t)i * FF_ * H_;
        const float* bq_i = bq + i * H_;
        const float* bk_i = bk + i * H_;
        const float* bv_i = bv + i * H_;
        const float* bo_i = bo + i * H_;
        const float* b1_i = b1 + i * FF_;
        const float* b2_i = b2 + i * H_;
        const float* g_i  = gamma + i * H_;
        const float* be_i = beta  + i * H_;
        float* xout = (i == L_ - 1) ? (float*)d_out : x;

        // fused QKV projections (A = rounded x), outputs rounded for flash
        gemm_tc_kernel<false, true><<<gQKV, 256, GEMM_SMEM>>>(
            xr, Wq_i, Wk_i, Wv_i, bq_i, bk_i, bv_i, q, k, v, M_, H_, H_);

        flash_kernel<<<gFlash, 256, FLASH_SMEM>>>(q, k, v, mb, t);

        // O projection, split-K=2 -> t2a + t2b
        gemm_tc_sk<<<gSK, 256, GEMM_SMEM>>>(t, Wo_i, bo_i, t2a, t2b, M_, H_, H_);
        add_ln_kernel<<<M_, 256>>>(x, t2a, t2b, g_i, be_i, res, resr);

        gemm_tc_kernel<true, true><<<gFfn1, 256, GEMM_SMEM>>>(
            resr, W1_i, W1_i, W1_i, b1_i, b1_i, b1_i, h1, h1, h1, M_, FF_, H_);

        // FFN2, split-K=2 -> t2a + t2b
        gemm_tc_sk<<<gSK, 256, GEMM_SMEM>>>(h1, W2_i, b2_i, t2a, t2b, M_, H_, FF_);
        add_ln_kernel<<<M_, 256>>>(res, t2a, t2b, g_i, be_i, xout, xr);
    }
}